// round 3
// baseline (speedup 1.0000x reference)
#include <cuda_runtime.h>
#include <math.h>

#define BB   4
#define NN   4096
#define CC   128
#define KK1  16
#define KK2  8
#define TDD  64
#define KDIM 131
#define KPAD 144
#define RWS  384
#define NPTS (BB*NN)

// ---------------- scratch (static device globals; no runtime alloc) ----------------
__device__ int   g_idx[NPTS*KK1];              // per point: 16 neighbor local indices
__device__ float g_P[(size_t)NPTS*RWS];        // per point: [0:64)Pq [64:192)Pk|Pv [192:384)Sq|Sk|Sv
__device__ float g_WcT[KPAD*RWS];              // K-major combined weights (zero-padded K rows)
__device__ float g_bias[RWS];
__device__ float g_w1T[TDD*CC];                // w1 transposed: [m][o]

// ---------------- prep: build combined weights ----------------
__global__ void prep_kernel(const float* __restrict__ wq, const float* __restrict__ wk,
                            const float* __restrict__ wv, const float* __restrict__ bq,
                            const float* __restrict__ bk, const float* __restrict__ bv,
                            const float* __restrict__ w1) {
    int i = blockIdx.x * blockDim.x + threadIdx.x;
    const int total1 = KPAD * RWS;
    if (i < total1) {
        int k = i / RWS;
        int r = i - k * RWS;
        float val = 0.f;
        if (k < KDIM) {
            int seg = r >> 6;         // 0:Pq 1:Pk 2:Pv 3:Sq 4:Sk 5:Sv
            int o   = r & 63;
            const float* w = (seg == 0 || seg == 3) ? wq : (seg == 1 || seg == 4) ? wk : wv;
            const float* row = w + o * 262;
            if (seg < 3) {
                val = (k < 3) ? row[k] : row[6 + (k - 3)];
            } else {
                val = (k < 3) ? (row[3 + k] - row[k])
                              : (row[134 + (k - 3)] - row[6 + (k - 3)]);
            }
        }
        g_WcT[k * RWS + r] = val;
        return;
    }
    i -= total1;
    if (i < RWS) {
        int seg = i >> 6, o = i & 63;
        float bv_ = 0.f;
        if (seg == 3) bv_ = bq[o];
        else if (seg == 4) bv_ = bk[o];
        else if (seg == 5) bv_ = bv[o];
        g_bias[i] = bv_;
        return;
    }
    i -= RWS;
    if (i < TDD * CC) {
        int m = i / CC, o = i - m * CC;
        g_w1T[m * CC + o] = w1[o * TDD + m];
    }
}

// ---------------- brute-force exact kNN (top-16 excl self) ----------------
__global__ void knn_kernel(const float* __restrict__ xyz) {
    extern __shared__ float4 sh[];                 // 4096 * (x,y,z,|x|^2) = 64KB
    const int b = blockIdx.x >> 5;
    const int local = ((blockIdx.x & 31) << 7) + threadIdx.x;
    const float* xb = xyz + (size_t)b * 3 * NN;
    for (int i = threadIdx.x; i < NN; i += 128) {
        float x = xb[i], y = xb[NN + i], z = xb[2 * NN + i];
        float sq = fmaf(z, z, fmaf(y, y, x * x));
        sh[i] = make_float4(x, y, z, sq);
    }
    __syncthreads();

    const float4 q = sh[local];
    const float INF = __int_as_float(0x7f800000);
    float dl[KK1];
    int   il[KK1];
#pragma unroll
    for (int s = 0; s < KK1; ++s) { dl[s] = 3.4e38f; il[s] = 0; }

#pragma unroll 4
    for (int m = 0; m < NN; ++m) {
        float4 c = sh[m];
        float t = q.x * c.x;
        t = fmaf(q.y, c.y, t);
        t = fmaf(q.z, c.z, t);
        float d = (q.w + c.w) - 2.0f * t;      // matches reference fp32 formula
        if (m == local) d = INF;               // exclude self (== dropping ref idx[...,0])
        if (d < dl[KK1 - 1]) {
            float dd = d; int ii = m;
#pragma unroll
            for (int s = 0; s < KK1; ++s) {
                if (dd < dl[s]) {              // strict < => stable tie-break (lower idx first)
                    float td = dl[s]; int ti = il[s];
                    dl[s] = dd; il[s] = ii; dd = td; ii = ti;
                }
            }
        }
    }
    int* op = g_idx + ((size_t)b * NN + local) * KK1;
#pragma unroll
    for (int s = 0; s < KK1; ++s) op[s] = il[s];
}

// ---------------- SGEMM: g_P[p][r] = sum_k WcT[k][r] * U[k][p] + bias[r] ----------------
// U rows: 0..2 = xyz rows, 3..130 = feature rows. M=384 rows, 16384 points.
__global__ void gemm_kernel(const float* __restrict__ xyz, const float* __restrict__ feature) {
    __shared__ __align__(16) float As[16][128];   // [k][row]
    __shared__ __align__(16) float Bs[16][64];    // [k][point]

    const int tid = threadIdx.x;
    const int tr = tid >> 4;            // 0..15 -> 8 rows each
    const int tc = tid & 15;            // 0..15 -> 4 points each
    const int p0 = blockIdx.x * 64;     // global point base (tiles never cross batch)
    const int b  = p0 >> 12;
    const int nl = p0 & (NN - 1);
    const int rowbase = blockIdx.y * 128;

    // load indices for As: each thread loads 8 consecutive floats of one k-row
    const int la_k = tid >> 4;          // 0..15
    const int la_r = (tid & 15) * 8;    // 0..120
    // Bs: each thread loads one float4 of one k-row
    const int lb_k = tid >> 4;
    const int lb_j = (tid & 15) * 4;

    float acc[8][4];
#pragma unroll
    for (int i = 0; i < 8; ++i)
#pragma unroll
        for (int j = 0; j < 4; ++j) acc[i][j] = 0.f;

    for (int kt = 0; kt < KPAD / 16; ++kt) {
        __syncthreads();
        // As tile
        {
            const float* src = g_WcT + (kt * 16 + la_k) * RWS + rowbase + la_r;
            *(float4*)&As[la_k][la_r]     = *(const float4*)src;
            *(float4*)&As[la_k][la_r + 4] = *(const float4*)(src + 4);
        }
        // Bs tile (from raw inputs, zero-padded K)
        {
            int kg = kt * 16 + lb_k;
            float4 v = make_float4(0.f, 0.f, 0.f, 0.f);
            if (kg < KDIM) {
                const float* row = (kg < 3)
                    ? (xyz + ((size_t)b * 3 + kg) * NN)
                    : (feature + ((size_t)b * CC + (kg - 3)) * NN);
                v = *(const float4*)(row + nl + lb_j);
            }
            *(float4*)&Bs[lb_k][lb_j] = v;
        }
        __syncthreads();
#pragma unroll
        for (int k = 0; k < 16; ++k) {
            float4 a0 = *(const float4*)&As[k][tr * 8];
            float4 a1 = *(const float4*)&As[k][tr * 8 + 4];
            float4 bb = *(const float4*)&Bs[k][tc * 4];
            float ar[8] = {a0.x, a0.y, a0.z, a0.w, a1.x, a1.y, a1.z, a1.w};
            float br[4] = {bb.x, bb.y, bb.z, bb.w};
#pragma unroll
            for (int i = 0; i < 8; ++i)
#pragma unroll
                for (int j = 0; j < 4; ++j)
                    acc[i][j] = fmaf(ar[i], br[j], acc[i][j]);
        }
    }

    // epilogue: point-major scatter with bias
    const int gr = rowbase + tr * 8;
    float bias[8];
#pragma unroll
    for (int i = 0; i < 8; ++i) bias[i] = g_bias[gr + i];
#pragma unroll
    for (int j = 0; j < 4; ++j) {
        int p = p0 + tc * 4 + j;
        float* dst = g_P + (size_t)p * RWS + gr;
        float4 v0 = make_float4(acc[0][j] + bias[0], acc[1][j] + bias[1],
                                acc[2][j] + bias[2], acc[3][j] + bias[3]);
        float4 v1 = make_float4(acc[4][j] + bias[4], acc[5][j] + bias[5],
                                acc[6][j] + bias[6], acc[7][j] + bias[7]);
        *(float4*)dst       = v0;
        *(float4*)(dst + 4) = v1;
    }
}

// ---------------- attention + output projection (warp per point, 8 points/block) --------
// smem floats: w1T 8192 | qs 8*(8*68) | kvs 8*(16*132) | resT 64*8 | ws 8*16
#define SM_QS   8192
#define SM_KVS  (SM_QS + 8*8*68)
#define SM_REST (SM_KVS + 8*16*132)
#define SM_WS   (SM_REST + 64*8)
#define SM_TOT  (SM_WS + 8*16)

__global__ void attn_kernel(const float* __restrict__ feature, const float* __restrict__ b1,
                            float* __restrict__ out) {
    extern __shared__ __align__(16) float sm[];
    float* w1T_s = sm;
    float* resT  = sm + SM_REST;
    float* wssm  = sm + SM_WS;

    const int tid = threadIdx.x;
    const int w = tid >> 5, l = tid & 31;

    for (int i = tid; i < TDD * CC; i += 256) w1T_s[i] = g_w1T[i];

    const int gp = blockIdx.x * 8 + w;
    const int b  = gp >> 12;
    const int*   ip = g_idx + (size_t)gp * KK1;
    const float* Sp = g_P + (size_t)gp * RWS + 192;
    float* qw  = sm + SM_QS  + w * (8 * 68);
    float* kvw = sm + SM_KVS + w * (16 * 132);

    // ---- gather q = Pq[c] + Sq ----
    {
        int a = l >> 2, qt = l & 3;
        int c = ip[a];
        const float4* src = (const float4*)(g_P + ((size_t)(b << 12) + c) * RWS) + qt * 4;
        const float4* s4  = (const float4*)(Sp) + qt * 4;
        float4* dst = (float4*)(qw + a * 68 + qt * 16);
#pragma unroll
        for (int f = 0; f < 4; ++f) {
            float4 p = src[f], s = s4[f];
            dst[f] = make_float4(p.x + s.x, p.y + s.y, p.z + s.z, p.w + s.w);
        }
    }
    // ---- gather kv = Pkv[c] + (Sk|Sv) ----
    {
        int j = l >> 1, h = l & 1;
        int c = ip[j];
        const float4* src = (const float4*)(g_P + ((size_t)(b << 12) + c) * RWS + 64 + h * 64);
        const float4* s4  = (const float4*)(Sp + 64 + h * 64);
        float4* dst = (float4*)(kvw + j * 132 + h * 64);
#pragma unroll
        for (int f = 0; f < 16; ++f) {
            float4 p = src[f], s = s4[f];
            dst[f] = make_float4(p.x + s.x, p.y + s.y, p.z + s.z, p.w + s.w);
        }
    }
    __syncwarp();

    // ---- logits: lane (nq = l&7, jg = l>>3) computes j = j4*4+jg ----
    const int nq = l & 7, jg = l >> 3;
    float acc[4] = {0.f, 0.f, 0.f, 0.f};
    const float4* qrow = (const float4*)(qw + nq * 68);
#pragma unroll
    for (int dc = 0; dc < 4; ++dc) {
        float4 q0 = qrow[dc * 4 + 0], q1 = qrow[dc * 4 + 1];
        float4 q2 = qrow[dc * 4 + 2], q3 = qrow[dc * 4 + 3];
#pragma unroll
        for (int j4 = 0; j4 < 4; ++j4) {
            const float4* kr = (const float4*)(kvw + (j4 * 4 + jg) * 132);
            float4 k0 = kr[dc * 4 + 0], k1 = kr[dc * 4 + 1];
            float4 k2 = kr[dc * 4 + 2], k3 = kr[dc * 4 + 3];
            float s = q0.x * k0.x;
            s = fmaf(q0.y, k0.y, s); s = fmaf(q0.z, k0.z, s); s = fmaf(q0.w, k0.w, s);
            s = fmaf(q1.x, k1.x, s); s = fmaf(q1.y, k1.y, s); s = fmaf(q1.z, k1.z, s); s = fmaf(q1.w, k1.w, s);
            s = fmaf(q2.x, k2.x, s); s = fmaf(q2.y, k2.y, s); s = fmaf(q2.z, k2.z, s); s = fmaf(q2.w, k2.w, s);
            s = fmaf(q3.x, k3.x, s); s = fmaf(q3.y, k3.y, s); s = fmaf(q3.z, k3.z, s); s = fmaf(q3.w, k3.w, s);
            acc[j4] += s;
        }
    }

    // ---- softmax over j (lanes {nq, nq+8, nq+16, nq+24} hold row nq) ----
    float mx = fmaxf(fmaxf(acc[0], acc[1]), fmaxf(acc[2], acc[3]));
    mx = fmaxf(mx, __shfl_xor_sync(0xffffffffu, mx, 8));
    mx = fmaxf(mx, __shfl_xor_sync(0xffffffffu, mx, 16));
    float e[4], ssum = 0.f;
#pragma unroll
    for (int j4 = 0; j4 < 4; ++j4) { e[j4] = __expf(acc[j4] - mx); ssum += e[j4]; }
    ssum += __shfl_xor_sync(0xffffffffu, ssum, 8);
    ssum += __shfl_xor_sync(0xffffffffu, ssum, 16);
    float inv = 1.0f / ssum;
    float wj[4];
#pragma unroll
    for (int j4 = 0; j4 < 4; ++j4) wj[j4] = e[j4] * inv;

    // ---- colsum over the 8 queries (lanes jg*8 .. jg*8+7) ----
#pragma unroll
    for (int off = 1; off < 8; off <<= 1)
#pragma unroll
        for (int j4 = 0; j4 < 4; ++j4)
            wj[j4] += __shfl_xor_sync(0xffffffffu, wj[j4], off);
    if (nq == 0) {
#pragma unroll
        for (int j4 = 0; j4 < 4; ++j4) wssm[w * 16 + j4 * 4 + jg] = wj[j4];
    }
    __syncwarp();

    // ---- res[64] = sum_j w[j] * v[j] (lane owns dims 2l, 2l+1) ----
    float r0 = 0.f, r1 = 0.f;
    const float* wsw = wssm + w * 16;
#pragma unroll
    for (int j = 0; j < 16; ++j) {
        float wv_ = wsw[j];
        float2 vv = *(const float2*)(kvw + j * 132 + 64 + 2 * l);
        r0 = fmaf(wv_, vv.x, r0);
        r1 = fmaf(wv_, vv.y, r1);
    }
    resT[(2 * l) * 8 + w]     = r0;
    resT[(2 * l + 1) * 8 + w] = r1;
    __syncthreads();

    // ---- out = w1 @ res + b1 + feature (block-wide, coalesced float4 stores) ----
    const int o  = tid >> 1;
    const int pg = (tid & 1) * 4;
    float a0 = 0.f, a1 = 0.f, a2 = 0.f, a3 = 0.f;
#pragma unroll
    for (int m = 0; m < 64; ++m) {
        float wv_ = w1T_s[m * CC + o];
        float4 rv = *(const float4*)(resT + m * 8 + pg);
        a0 = fmaf(wv_, rv.x, a0);
        a1 = fmaf(wv_, rv.y, a1);
        a2 = fmaf(wv_, rv.z, a2);
        a3 = fmaf(wv_, rv.w, a3);
    }
    const int gp0 = blockIdx.x * 8;
    const int bb = gp0 >> 12, nl = gp0 & (NN - 1);
    size_t base = ((size_t)bb * CC + o) * NN + nl + pg;
    float4 fv = *(const float4*)(feature + base);
    float bo = b1[o];
    float4 ov = make_float4(a0 + bo + fv.x, a1 + bo + fv.y, a2 + bo + fv.z, a3 + bo + fv.w);
    *(float4*)(out + base) = ov;
}

// ---------------- launch ----------------
extern "C" void kernel_launch(void* const* d_in, const int* in_sizes, int n_in,
                              void* d_out, int out_size) {
    const float* feature = (const float*)d_in[0];
    const float* xyz     = (const float*)d_in[1];
    const float* wq      = (const float*)d_in[2];
    const float* bq      = (const float*)d_in[3];
    const float* wk      = (const float*)d_in[4];
    const float* bk      = (const float*)d_in[5];
    const float* wv      = (const float*)d_in[6];
    const float* bv      = (const float*)d_in[7];
    const float* w1      = (const float*)d_in[8];
    const float* b1      = (const float*)d_in[9];
    float* out = (float*)d_out;

    cudaFuncSetAttribute(knn_kernel,  cudaFuncAttributeMaxDynamicSharedMemorySize, NN * 16);
    cudaFuncSetAttribute(attn_kernel, cudaFuncAttributeMaxDynamicSharedMemorySize, SM_TOT * 4);

    {
        int total = KPAD * RWS + RWS + TDD * CC;
        prep_kernel<<<(total + 255) / 256, 256>>>(wq, wk, wv, bq, bk, bv, w1);
    }
    knn_kernel<<<BB * 32, 128, NN * 16>>>(xyz);
    gemm_kernel<<<dim3(NPTS / 64, RWS / 128), 256>>>(xyz, feature);
    attn_kernel<<<NPTS / 8, 256, SM_TOT * 4>>>(feature, b1, out);
}

// round 4
// speedup vs baseline: 1.1404x; 1.1404x over previous
#include <cuda_runtime.h>
#include <math.h>

#define BB   4
#define NN   4096
#define CC   128
#define KK1  16
#define KK2  8
#define TDD  64
#define KDIM 131
#define KPAD 144
#define RWS  512
#define NPTS (BB*NN)

// ---------------- scratch (static device globals) ----------------
__device__ int   g_idx[NPTS*KK1];
// per point rows: [0:64)Pq [64:128)Pk [128:256)PvProj [256:320)Sq [320:384)Sk [384:512)SvProj
__device__ float g_P[(size_t)NPTS*RWS];
__device__ float g_WcT[KPAD*RWS];              // K-major combined weights (zero-padded K rows)
__device__ float g_bias[RWS];

// ---------------- prep: build combined (w1-folded) weights ----------------
__global__ void prep_kernel(const float* __restrict__ wq, const float* __restrict__ wk,
                            const float* __restrict__ wv, const float* __restrict__ bq,
                            const float* __restrict__ bk, const float* __restrict__ bv,
                            const float* __restrict__ w1) {
    int i = blockIdx.x * blockDim.x + threadIdx.x;
    const int total1 = KPAD * RWS;
    if (i < total1) {
        int k = i >> 9;
        int r = i & 511;
        float val = 0.f;
        if (k < KDIM) {
            if (r < 128) {                       // Pq | Pk
                const float* w = (r < 64) ? wq : wk;
                const float* row = w + (r & 63) * 262;
                val = (k < 3) ? row[k] : row[6 + (k - 3)];
            } else if (r < 256) {                // PvProj = w1 @ Pv
                int o = r - 128;
                float s = 0.f;
                for (int m = 0; m < TDD; ++m) {
                    const float* row = wv + m * 262;
                    float wvk = (k < 3) ? row[k] : row[6 + (k - 3)];
                    s = fmaf(w1[o * TDD + m], wvk, s);
                }
                val = s;
            } else if (r < 384) {                // Sq | Sk
                const float* w = (r < 320) ? wq : wk;
                const float* row = w + (r & 63) * 262;
                val = (k < 3) ? (row[3 + k] - row[k])
                              : (row[134 + (k - 3)] - row[6 + (k - 3)]);
            } else {                             // SvProj = w1 @ Sv
                int o = r - 384;
                float s = 0.f;
                for (int m = 0; m < TDD; ++m) {
                    const float* row = wv + m * 262;
                    float d = (k < 3) ? (row[3 + k] - row[k])
                                      : (row[134 + (k - 3)] - row[6 + (k - 3)]);
                    s = fmaf(w1[o * TDD + m], d, s);
                }
                val = s;
            }
        }
        g_WcT[(k << 9) + r] = val;
        return;
    }
    i -= total1;
    if (i < RWS) {
        float bval = 0.f;
        if (i >= 256 && i < 320) bval = bq[i - 256];
        else if (i >= 320 && i < 384) bval = bk[i - 320];
        else if (i >= 384) {
            int o = i - 384;
            float s = 0.f;
            for (int m = 0; m < TDD; ++m) s = fmaf(w1[o * TDD + m], bv[m], s);
            bval = s;
        }
        g_bias[i] = bval;
    }
}

// ---------------- chunked brute-force exact kNN (top-16 excl self) ----------------
// block = 128 threads: 4 warps (= 4 candidate chunks of 1024) x 32 queries.
__global__ void knn_kernel(const float* __restrict__ xyz) {
    extern __shared__ __align__(16) float smraw[];
    float4* sh = (float4*)smraw;                         // 4096 * 16B = 64KB
    float*  sd = smraw + NN * 4;                         // [4][32][17] dists
    int*    si = (int*)(sd + 4 * 32 * 17);               // [4][32][17] indices

    const int b = blockIdx.x >> 7;
    const int qbase = (blockIdx.x & 127) * 32;
    const int tid = threadIdx.x;
    const int w = tid >> 5, lane = tid & 31;
    const float* xb = xyz + (size_t)b * 3 * NN;

    for (int i = tid; i < NN; i += 128) {
        float x = xb[i], y = xb[NN + i], z = xb[2 * NN + i];
        float sq = fmaf(z, z, fmaf(y, y, x * x));
        sh[i] = make_float4(x, y, z, sq);
    }
    __syncthreads();

    const int local = qbase + lane;
    const float4 q = sh[local];
    const float INF = __int_as_float(0x7f800000);
    float dl[KK1];
    int   il[KK1];
#pragma unroll
    for (int s = 0; s < KK1; ++s) { dl[s] = 3.4e38f; il[s] = 0; }

    const int m0 = w * (NN / 4);
#pragma unroll 4
    for (int mm = 0; mm < NN / 4; ++mm) {
        int m = m0 + mm;
        float4 c = sh[m];
        float t = q.x * c.x;
        t = fmaf(q.y, c.y, t);
        t = fmaf(q.z, c.z, t);
        float d = (q.w + c.w) - 2.0f * t;
        if (m == local) d = INF;
        if (d < dl[KK1 - 1]) {
            float dd = d; int ii = m;
#pragma unroll
            for (int s = 0; s < KK1; ++s) {
                if (dd < dl[s]) {
                    float td = dl[s]; int ti = il[s];
                    dl[s] = dd; il[s] = ii; dd = td; ii = ti;
                }
            }
        }
    }
    {
        int base = (w * 32 + lane) * 17;
#pragma unroll
        for (int s = 0; s < KK1; ++s) { sd[base + s] = dl[s]; si[base + s] = il[s]; }
    }
    __syncthreads();

    if (w == 0) {
        int p0 = 0, p1 = 0, p2 = 0, p3 = 0;
        const int b0 = (0 * 32 + lane) * 17, b1 = (1 * 32 + lane) * 17;
        const int b2 = (2 * 32 + lane) * 17, b3 = (3 * 32 + lane) * 17;
        int* op = g_idx + ((size_t)b * NN + local) * KK1;
#pragma unroll
        for (int s = 0; s < KK1; ++s) {
            float d0 = (p0 < 16) ? sd[b0 + p0] : INF;
            float d1 = (p1 < 16) ? sd[b1 + p1] : INF;
            float d2 = (p2 < 16) ? sd[b2 + p2] : INF;
            float d3 = (p3 < 16) ? sd[b3 + p3] : INF;
            // strict <, chunk order = index order => correct tie-break
            int bc = 0; float bd = d0;
            if (d1 < bd) { bd = d1; bc = 1; }
            if (d2 < bd) { bd = d2; bc = 2; }
            if (d3 < bd) { bd = d3; bc = 3; }
            int outi;
            if      (bc == 0) { outi = si[b0 + p0]; ++p0; }
            else if (bc == 1) { outi = si[b1 + p1]; ++p1; }
            else if (bc == 2) { outi = si[b2 + p2]; ++p2; }
            else              { outi = si[b3 + p3]; ++p3; }
            op[s] = outi;
        }
    }
}

// ---------------- SGEMM: g_P[p][r] = sum_k WcT[k][r] * U[k][p] + bias[r] ----------------
// BM=128 rows, BN=128 points, BK=16; 8x8 micro-tile; register double-buffered loads.
__global__ __launch_bounds__(256) void gemm_kernel(const float* __restrict__ xyz,
                                                   const float* __restrict__ feature) {
    __shared__ __align__(16) float As[16][128];
    __shared__ __align__(16) float Bs[16][128];

    const int tid = threadIdx.x;
    const int tr = tid >> 4;
    const int tc = tid & 15;
    const int p0 = blockIdx.x * 128;
    const int b  = p0 >> 12;
    const int nl = p0 & (NN - 1);
    const int rowbase = blockIdx.y * 128;

    const int la_k = tid >> 4;
    const int la_r = (tid & 15) * 8;
    const int lb_k = tid >> 4;
    const int lb_j = (tid & 15) * 8;

    float acc[8][8];
#pragma unroll
    for (int i = 0; i < 8; ++i)
#pragma unroll
        for (int j = 0; j < 8; ++j) acc[i][j] = 0.f;

    float4 pa0, pa1, pb0, pb1;
    {   // prefetch tile 0
        const float* srcA = g_WcT + (0 * 16 + la_k) * RWS + rowbase + la_r;
        pa0 = *(const float4*)srcA; pa1 = *(const float4*)(srcA + 4);
        int kg = lb_k;
        const float* row = (kg < 3) ? (xyz + ((size_t)b * 3 + kg) * NN)
                                    : (feature + ((size_t)b * CC + (kg - 3)) * NN);
        pb0 = *(const float4*)(row + nl + lb_j);
        pb1 = *(const float4*)(row + nl + lb_j + 4);
    }

    for (int kt = 0; kt < KPAD / 16; ++kt) {
        *(float4*)&As[la_k][la_r]     = pa0;
        *(float4*)&As[la_k][la_r + 4] = pa1;
        *(float4*)&Bs[lb_k][lb_j]     = pb0;
        *(float4*)&Bs[lb_k][lb_j + 4] = pb1;
        __syncthreads();
        if (kt + 1 < KPAD / 16) {
            const float* srcA = g_WcT + ((kt + 1) * 16 + la_k) * RWS + rowbase + la_r;
            pa0 = *(const float4*)srcA; pa1 = *(const float4*)(srcA + 4);
            int kg = (kt + 1) * 16 + lb_k;
            if (kg < KDIM) {
                const float* row = (kg < 3) ? (xyz + ((size_t)b * 3 + kg) * NN)
                                            : (feature + ((size_t)b * CC + (kg - 3)) * NN);
                pb0 = *(const float4*)(row + nl + lb_j);
                pb1 = *(const float4*)(row + nl + lb_j + 4);
            } else {
                pb0 = make_float4(0.f, 0.f, 0.f, 0.f);
                pb1 = pb0;
            }
        }
#pragma unroll
        for (int k = 0; k < 16; ++k) {
            float4 a0 = *(const float4*)&As[k][tr * 8];
            float4 a1 = *(const float4*)&As[k][tr * 8 + 4];
            float4 c0 = *(const float4*)&Bs[k][tc * 8];
            float4 c1 = *(const float4*)&Bs[k][tc * 8 + 4];
            float ar[8] = {a0.x, a0.y, a0.z, a0.w, a1.x, a1.y, a1.z, a1.w};
            float br[8] = {c0.x, c0.y, c0.z, c0.w, c1.x, c1.y, c1.z, c1.w};
#pragma unroll
            for (int i = 0; i < 8; ++i)
#pragma unroll
                for (int j = 0; j < 8; ++j)
                    acc[i][j] = fmaf(ar[i], br[j], acc[i][j]);
        }
        __syncthreads();
    }

    const int gr = rowbase + tr * 8;
    float bias[8];
#pragma unroll
    for (int i = 0; i < 8; ++i) bias[i] = g_bias[gr + i];
#pragma unroll
    for (int j = 0; j < 8; ++j) {
        int p = p0 + tc * 8 + j;
        float* dst = g_P + (size_t)p * RWS + gr;
        float4 v0 = make_float4(acc[0][j] + bias[0], acc[1][j] + bias[1],
                                acc[2][j] + bias[2], acc[3][j] + bias[3]);
        float4 v1 = make_float4(acc[4][j] + bias[4], acc[5][j] + bias[5],
                                acc[6][j] + bias[6], acc[7][j] + bias[7]);
        *(float4*)dst       = v0;
        *(float4*)(dst + 4) = v1;
    }
}

// ---------------- attention (warp per point, 8 points/block) ----------------
// per-warp smem: q[8][68] + k[16][68] = 1632 floats; block: 8*1632 + resT[8][132]
#define WARP_FLOATS 1632
#define SM_RES      (8*WARP_FLOATS)
#define SM_ATTN_TOT (SM_RES + 8*132)

__global__ __launch_bounds__(256) void attn_kernel(const float* __restrict__ feature,
                                                   const float* __restrict__ b1,
                                                   float* __restrict__ out) {
    extern __shared__ __align__(16) float sm[];
    const int tid = threadIdx.x;
    const int w = tid >> 5, l = tid & 31;
    float* qw   = sm + w * WARP_FLOATS;
    float* kw   = qw + 8 * 68;
    float* resT = sm + SM_RES;

    const int gp = blockIdx.x * 8 + w;
    const int b  = gp >> 12;
    const int* ip = g_idx + (size_t)gp * KK1;
    const float* Pbase = g_P + ((size_t)(b << 12)) * RWS;
    const float* Sp    = g_P + (size_t)gp * RWS + 256;

    int c[16];
    {
        int4 t0 = ((const int4*)ip)[0]; int4 t1 = ((const int4*)ip)[1];
        int4 t2 = ((const int4*)ip)[2]; int4 t3 = ((const int4*)ip)[3];
        c[0]=t0.x; c[1]=t0.y; c[2]=t0.z; c[3]=t0.w;
        c[4]=t1.x; c[5]=t1.y; c[6]=t1.z; c[7]=t1.w;
        c[8]=t2.x; c[9]=t2.y; c[10]=t2.z; c[11]=t2.w;
        c[12]=t3.x; c[13]=t3.y; c[14]=t3.z; c[15]=t3.w;
    }

    // ---- gather q = Pq[c] + Sq ----
    {
        int a = l >> 2, qt = l & 3;
        const float4* src = (const float4*)(Pbase + (size_t)c[a] * RWS) + qt * 4;
        const float4* s4  = (const float4*)Sp + qt * 4;
        float4* dst = (float4*)(qw + a * 68 + qt * 16);
#pragma unroll
        for (int f = 0; f < 4; ++f) {
            float4 p = src[f], s = s4[f];
            dst[f] = make_float4(p.x + s.x, p.y + s.y, p.z + s.z, p.w + s.w);
        }
    }
    // ---- gather k = Pk[c] + Sk ----
    {
        int j = l >> 1, h = l & 1;
        const float4* src = (const float4*)(Pbase + (size_t)c[j] * RWS + 64 + h * 32);
        const float4* s4  = (const float4*)(Sp + 64 + h * 32);
        float4* dst = (float4*)(kw + j * 68 + h * 32);
#pragma unroll
        for (int f = 0; f < 8; ++f) {
            float4 p = src[f], s = s4[f];
            dst[f] = make_float4(p.x + s.x, p.y + s.y, p.z + s.z, p.w + s.w);
        }
    }
    __syncwarp();

    // ---- logits: lane (nq = l&7, jg = l>>3) computes j = j4*4+jg ----
    const int nq = l & 7, jg = l >> 3;
    float acc[4] = {0.f, 0.f, 0.f, 0.f};
    const float4* qrow = (const float4*)(qw + nq * 68);
#pragma unroll
    for (int dc = 0; dc < 4; ++dc) {
        float4 q0 = qrow[dc * 4 + 0], q1 = qrow[dc * 4 + 1];
        float4 q2 = qrow[dc * 4 + 2], q3 = qrow[dc * 4 + 3];
#pragma unroll
        for (int j4 = 0; j4 < 4; ++j4) {
            const float4* kr = (const float4*)(kw + (j4 * 4 + jg) * 68);
            float4 k0 = kr[dc * 4 + 0], k1 = kr[dc * 4 + 1];
            float4 k2 = kr[dc * 4 + 2], k3 = kr[dc * 4 + 3];
            float s = q0.x * k0.x;
            s = fmaf(q0.y, k0.y, s); s = fmaf(q0.z, k0.z, s); s = fmaf(q0.w, k0.w, s);
            s = fmaf(q1.x, k1.x, s); s = fmaf(q1.y, k1.y, s); s = fmaf(q1.z, k1.z, s); s = fmaf(q1.w, k1.w, s);
            s = fmaf(q2.x, k2.x, s); s = fmaf(q2.y, k2.y, s); s = fmaf(q2.z, k2.z, s); s = fmaf(q2.w, k2.w, s);
            s = fmaf(q3.x, k3.x, s); s = fmaf(q3.y, k3.y, s); s = fmaf(q3.z, k3.z, s); s = fmaf(q3.w, k3.w, s);
            acc[j4] += s;
        }
    }

    // ---- softmax over j per query row nq ----
    float mx = fmaxf(fmaxf(acc[0], acc[1]), fmaxf(acc[2], acc[3]));
    mx = fmaxf(mx, __shfl_xor_sync(0xffffffffu, mx, 8));
    mx = fmaxf(mx, __shfl_xor_sync(0xffffffffu, mx, 16));
    float e[4], ssum = 0.f;
#pragma unroll
    for (int j4 = 0; j4 < 4; ++j4) { e[j4] = __expf(acc[j4] - mx); ssum += e[j4]; }
    ssum += __shfl_xor_sync(0xffffffffu, ssum, 8);
    ssum += __shfl_xor_sync(0xffffffffu, ssum, 16);
    float inv = 1.0f / ssum;
    float wj[4];
#pragma unroll
    for (int j4 = 0; j4 < 4; ++j4) wj[j4] = e[j4] * inv;

    // ---- colsum over the 8 queries (all lanes end holding colsum for their jg) ----
#pragma unroll
    for (int off = 1; off < 8; off <<= 1)
#pragma unroll
        for (int j4 = 0; j4 < 4; ++j4)
            wj[j4] += __shfl_xor_sync(0xffffffffu, wj[j4], off);

    // ---- res128 = sum_j w[j] * PvProj[c_j] + (sum_j w[j]) * SvProj; lane owns 4 channels ----
    float4 av = make_float4(0.f, 0.f, 0.f, 0.f);
#pragma unroll
    for (int j = 0; j < 16; ++j) {
        float wjv = __shfl_sync(0xffffffffu, wj[j >> 2], (j & 3) * 8);
        float4 vv = *(const float4*)(Pbase + (size_t)c[j] * RWS + 128 + 4 * l);
        av.x = fmaf(wjv, vv.x, av.x);
        av.y = fmaf(wjv, vv.y, av.y);
        av.z = fmaf(wjv, vv.z, av.z);
        av.w = fmaf(wjv, vv.w, av.w);
    }
    float wsum = wj[0] + wj[1] + wj[2] + wj[3];
    wsum += __shfl_xor_sync(0xffffffffu, wsum, 8);
    wsum += __shfl_xor_sync(0xffffffffu, wsum, 16);
    {
        float4 sv = *(const float4*)(Sp + 128 + 4 * l);   // SvProj (g_P row offset 384)
        av.x = fmaf(wsum, sv.x, av.x);
        av.y = fmaf(wsum, sv.y, av.y);
        av.z = fmaf(wsum, sv.z, av.z);
        av.w = fmaf(wsum, sv.w, av.w);
    }
    *(float4*)(resT + w * 132 + 4 * l) = av;
    __syncthreads();

    // ---- out = res + b1 + feature (coalesced float4 stores across 8 points) ----
    const int o  = tid >> 1;
    const int pg = (tid & 1) * 4;
    const int gp0 = blockIdx.x * 8;
    const int bb = gp0 >> 12, nl = gp0 & (NN - 1);
    size_t base = ((size_t)bb * CC + o) * NN + nl + pg;
    float bo = b1[o];
    float4 fv = *(const float4*)(feature + base);
    float4 ov;
    ov.x = resT[(pg + 0) * 132 + o] + bo + fv.x;
    ov.y = resT[(pg + 1) * 132 + o] + bo + fv.y;
    ov.z = resT[(pg + 2) * 132 + o] + bo + fv.z;
    ov.w = resT[(pg + 3) * 132 + o] + bo + fv.w;
    *(float4*)(out + base) = ov;
}

// ---------------- launch ----------------
extern "C" void kernel_launch(void* const* d_in, const int* in_sizes, int n_in,
                              void* d_out, int out_size) {
    const float* feature = (const float*)d_in[0];
    const float* xyz     = (const float*)d_in[1];
    const float* wq      = (const float*)d_in[2];
    const float* bq      = (const float*)d_in[3];
    const float* wk      = (const float*)d_in[4];
    const float* bk      = (const float*)d_in[5];
    const float* wv      = (const float*)d_in[6];
    const float* bv      = (const float*)d_in[7];
    const float* w1      = (const float*)d_in[8];
    const float* b1      = (const float*)d_in[9];
    float* out = (float*)d_out;

    const int knn_smem  = NN * 16 + 4 * 32 * 17 * 4 * 2;
    const int attn_smem = SM_ATTN_TOT * 4;
    cudaFuncSetAttribute(knn_kernel,  cudaFuncAttributeMaxDynamicSharedMemorySize, knn_smem);
    cudaFuncSetAttribute(attn_kernel, cudaFuncAttributeMaxDynamicSharedMemorySize, attn_smem);

    {
        int total = KPAD * RWS + RWS;
        prep_kernel<<<(total + 255) / 256, 256>>>(wq, wk, wv, bq, bk, bv, w1);
    }
    knn_kernel<<<BB * 128, 128, knn_smem>>>(xyz);
    gemm_kernel<<<dim3(NPTS / 128, RWS / 128), 256>>>(xyz, feature);
    attn_kernel<<<NPTS / 8, 256, attn_smem>>>(feature, b1, out);
}

// round 5
// speedup vs baseline: 1.4044x; 1.2316x over previous
#include <cuda_runtime.h>
#include <math.h>

#define BB   4
#define NN   4096
#define CC   128
#define KK1  16
#define KK2  8
#define TDD  64
#define KDIM 131
#define KPAD 144
#define RWS  512
#define NPTS (BB*NN)

typedef unsigned long long u64;

__device__ __forceinline__ u64 ffma2(u64 a, u64 b, u64 c) {
    u64 d;
    asm("fma.rn.f32x2 %0, %1, %2, %3;" : "=l"(d) : "l"(a), "l"(b), "l"(c));
    return d;
}
__device__ __forceinline__ u64 dup2(float x) {
    u64 d;
    asm("mov.b64 %0, {%1, %1};" : "=l"(d) : "r"(__float_as_int(x)));
    return d;
}
__device__ __forceinline__ void unpack2(u64 v, float& lo, float& hi) {
    int a, b;
    asm("mov.b64 {%0, %1}, %2;" : "=r"(a), "=r"(b) : "l"(v));
    lo = __int_as_float(a); hi = __int_as_float(b);
}

// ---------------- scratch ----------------
__device__ int   g_idx[NPTS*KK1];
// per point rows: [0:64)Pq [64:128)Pk [128:256)PvProj [256:320)Sq [320:384)Sk [384:512)SvProj
__device__ float g_P[(size_t)NPTS*RWS];
__device__ float g_WcT[KPAD*RWS];
__device__ float g_bias[RWS];

// ---------------- prep ----------------
__global__ void prep_kernel(const float* __restrict__ wq, const float* __restrict__ wk,
                            const float* __restrict__ wv, const float* __restrict__ bq,
                            const float* __restrict__ bk, const float* __restrict__ bv,
                            const float* __restrict__ w1) {
    int i = blockIdx.x * blockDim.x + threadIdx.x;
    const int total1 = KPAD * RWS;
    if (i < total1) {
        int k = i >> 9;
        int r = i & 511;
        float val = 0.f;
        if (k < KDIM) {
            if (r < 128) {                       // Pq | Pk
                const float* w = (r < 64) ? wq : wk;
                const float* row = w + (r & 63) * 262;
                val = (k < 3) ? row[k] : row[6 + (k - 3)];
            } else if (r < 256) {                // PvProj = w1 @ Pv
                int o = r - 128;
                float s = 0.f;
                for (int m = 0; m < TDD; ++m) {
                    const float* row = wv + m * 262;
                    float wvk = (k < 3) ? row[k] : row[6 + (k - 3)];
                    s = fmaf(w1[o * TDD + m], wvk, s);
                }
                val = s;
            } else if (r < 384) {                // Sq | Sk
                const float* w = (r < 320) ? wq : wk;
                const float* row = w + (r & 63) * 262;
                val = (k < 3) ? (row[3 + k] - row[k])
                              : (row[134 + (k - 3)] - row[6 + (k - 3)]);
            } else {                             // SvProj = w1 @ Sv
                int o = r - 384;
                float s = 0.f;
                for (int m = 0; m < TDD; ++m) {
                    const float* row = wv + m * 262;
                    float d = (k < 3) ? (row[3 + k] - row[k])
                                      : (row[134 + (k - 3)] - row[6 + (k - 3)]);
                    s = fmaf(w1[o * TDD + m], d, s);
                }
                val = s;
            }
        }
        g_WcT[(k << 9) + r] = val;
        return;
    }
    i -= total1;
    if (i < RWS) {
        float bval = 0.f;
        if (i >= 256 && i < 320) bval = bq[i - 256];
        else if (i >= 320 && i < 384) bval = bk[i - 320];
        else if (i >= 384) {
            int o = i - 384;
            float s = 0.f;
            for (int m = 0; m < TDD; ++m) s = fmaf(w1[o * TDD + m], bv[m], s);
            bval = s;
        }
        g_bias[i] = bval;
    }
}

// ---------------- kNN: full scan, uniform-branch + parallel branchless insert ------------
__global__ void knn_kernel(const float* __restrict__ xyz) {
    extern __shared__ float4 sh[];                 // 4096 * 16B = 64KB
    const int b = blockIdx.x >> 5;
    const int local = ((blockIdx.x & 31) << 7) + threadIdx.x;
    const float* xb = xyz + (size_t)b * 3 * NN;
    for (int i = threadIdx.x; i < NN; i += 128) {
        float x = xb[i], y = xb[NN + i], z = xb[2 * NN + i];
        float sq = fmaf(z, z, fmaf(y, y, x * x));
        sh[i] = make_float4(x, y, z, sq);
    }
    __syncthreads();

    const float4 q = sh[local];
    const float INF = __int_as_float(0x7f800000);
    float dl[KK1];
    int   il[KK1];
#pragma unroll
    for (int s = 0; s < KK1; ++s) { dl[s] = 3.4e38f; il[s] = 0; }

#pragma unroll 4
    for (int m = 0; m < NN; ++m) {
        float4 c = sh[m];
        float t = q.x * c.x;
        t = fmaf(q.y, c.y, t);
        t = fmaf(q.z, c.z, t);
        float d = fmaf(-2.0f, t, c.w);          // c.w - 2 q.c  (q.w const per query: dropped)
        if (m == local) d = INF;
        if (__any_sync(0xffffffffu, d < dl[KK1 - 1])) {
            // parallel shift-insert: each position depends only on OLD list
            bool cnd[KK1];
#pragma unroll
            for (int s = 0; s < KK1; ++s) cnd[s] = d < dl[s];
            float ndl[KK1]; int nil[KK1];
            ndl[0] = cnd[0] ? d : dl[0];
            nil[0] = cnd[0] ? m : il[0];
#pragma unroll
            for (int s = 1; s < KK1; ++s) {
                ndl[s] = cnd[s - 1] ? dl[s - 1] : (cnd[s] ? d : dl[s]);
                nil[s] = cnd[s - 1] ? il[s - 1] : (cnd[s] ? m : il[s]);
            }
#pragma unroll
            for (int s = 0; s < KK1; ++s) { dl[s] = ndl[s]; il[s] = nil[s]; }
        }
    }
    int* op = g_idx + ((size_t)b * NN + local) * KK1;
#pragma unroll
    for (int s = 0; s < KK1; ++s) op[s] = il[s];
}

// ---------------- SGEMM with packed f32x2 FMA ----------------
__global__ __launch_bounds__(256, 2) void gemm_kernel(const float* __restrict__ xyz,
                                                      const float* __restrict__ feature) {
    __shared__ __align__(16) float As[16][128];
    __shared__ __align__(16) float Bs[16][128];

    const int tid = threadIdx.x;
    const int tr = tid >> 4;
    const int tc = tid & 15;
    const int p0 = blockIdx.x * 128;
    const int b  = p0 >> 12;
    const int nl = p0 & (NN - 1);
    const int rowbase = blockIdx.y * 128;

    const int la_k = tid >> 4;
    const int la_r = (tid & 15) * 8;
    const int lb_k = tid >> 4;
    const int lb_j = (tid & 15) * 8;

    u64 acc[8][4];
#pragma unroll
    for (int i = 0; i < 8; ++i)
#pragma unroll
        for (int j = 0; j < 4; ++j) acc[i][j] = 0ull;

    float4 pa0, pa1, pb0, pb1;
    {
        const float* srcA = g_WcT + la_k * RWS + rowbase + la_r;
        pa0 = *(const float4*)srcA; pa1 = *(const float4*)(srcA + 4);
        int kg = lb_k;
        const float* row = (kg < 3) ? (xyz + ((size_t)b * 3 + kg) * NN)
                                    : (feature + ((size_t)b * CC + (kg - 3)) * NN);
        pb0 = *(const float4*)(row + nl + lb_j);
        pb1 = *(const float4*)(row + nl + lb_j + 4);
    }

    for (int kt = 0; kt < KPAD / 16; ++kt) {
        *(float4*)&As[la_k][la_r]     = pa0;
        *(float4*)&As[la_k][la_r + 4] = pa1;
        *(float4*)&Bs[lb_k][lb_j]     = pb0;
        *(float4*)&Bs[lb_k][lb_j + 4] = pb1;
        __syncthreads();
        if (kt + 1 < KPAD / 16) {
            const float* srcA = g_WcT + ((kt + 1) * 16 + la_k) * RWS + rowbase + la_r;
            pa0 = *(const float4*)srcA; pa1 = *(const float4*)(srcA + 4);
            int kg = (kt + 1) * 16 + lb_k;
            if (kg < KDIM) {
                const float* row = (kg < 3) ? (xyz + ((size_t)b * 3 + kg) * NN)
                                            : (feature + ((size_t)b * CC + (kg - 3)) * NN);
                pb0 = *(const float4*)(row + nl + lb_j);
                pb1 = *(const float4*)(row + nl + lb_j + 4);
            } else {
                pb0 = make_float4(0.f, 0.f, 0.f, 0.f);
                pb1 = pb0;
            }
        }
#pragma unroll
        for (int k = 0; k < 16; ++k) {
            float4 a0 = *(const float4*)&As[k][tr * 8];
            float4 a1 = *(const float4*)&As[k][tr * 8 + 4];
            ulonglong2 b0 = *(const ulonglong2*)&Bs[k][tc * 8];
            ulonglong2 b1 = *(const ulonglong2*)&Bs[k][tc * 8 + 4];
            u64 bp[4] = {b0.x, b0.y, b1.x, b1.y};
            float ar[8] = {a0.x, a0.y, a0.z, a0.w, a1.x, a1.y, a1.z, a1.w};
#pragma unroll
            for (int i = 0; i < 8; ++i) {
                u64 a2 = dup2(ar[i]);
#pragma unroll
                for (int j = 0; j < 4; ++j)
                    acc[i][j] = ffma2(a2, bp[j], acc[i][j]);
            }
        }
        __syncthreads();
    }

    const int gr = rowbase + tr * 8;
    float bias[8];
#pragma unroll
    for (int i = 0; i < 8; ++i) bias[i] = g_bias[gr + i];
    float r_[8][8];
#pragma unroll
    for (int i = 0; i < 8; ++i)
#pragma unroll
        for (int j = 0; j < 4; ++j)
            unpack2(acc[i][j], r_[i][2 * j], r_[i][2 * j + 1]);
#pragma unroll
    for (int j = 0; j < 8; ++j) {
        int p = p0 + tc * 8 + j;
        float* dst = g_P + (size_t)p * RWS + gr;
        float4 v0 = make_float4(r_[0][j] + bias[0], r_[1][j] + bias[1],
                                r_[2][j] + bias[2], r_[3][j] + bias[3]);
        float4 v1 = make_float4(r_[4][j] + bias[4], r_[5][j] + bias[5],
                                r_[6][j] + bias[6], r_[7][j] + bias[7]);
        *(float4*)dst       = v0;
        *(float4*)(dst + 4) = v1;
    }
}

// ---------------- attention ----------------
#define WARP_FLOATS 1632
#define SM_RES      (8*WARP_FLOATS)
#define SM_ATTN_TOT (SM_RES + 8*132)

__global__ __launch_bounds__(256, 3) void attn_kernel(const float* __restrict__ feature,
                                                      const float* __restrict__ b1,
                                                      float* __restrict__ out) {
    extern __shared__ __align__(16) float sm[];
    const int tid = threadIdx.x;
    const int w = tid >> 5, l = tid & 31;
    float* qw   = sm + w * WARP_FLOATS;
    float* kw   = qw + 8 * 68;
    float* resT = sm + SM_RES;

    const int gp = blockIdx.x * 8 + w;
    const int b  = gp >> 12;
    const int* ip = g_idx + (size_t)gp * KK1;
    const float* Pbase = g_P + ((size_t)(b << 12)) * RWS;
    const float* Sp    = g_P + (size_t)gp * RWS + 256;

    int c[16];
    {
        int4 t0 = ((const int4*)ip)[0]; int4 t1 = ((const int4*)ip)[1];
        int4 t2 = ((const int4*)ip)[2]; int4 t3 = ((const int4*)ip)[3];
        c[0]=t0.x; c[1]=t0.y; c[2]=t0.z; c[3]=t0.w;
        c[4]=t1.x; c[5]=t1.y; c[6]=t1.z; c[7]=t1.w;
        c[8]=t2.x; c[9]=t2.y; c[10]=t2.z; c[11]=t2.w;
        c[12]=t3.x; c[13]=t3.y; c[14]=t3.z; c[15]=t3.w;
    }

    // ---- gather q = Pq[c] + Sq ----
    {
        int a = l >> 2, qt = l & 3;
        const float4* src = (const float4*)(Pbase + (size_t)c[a] * RWS) + qt * 4;
        const float4* s4  = (const float4*)Sp + qt * 4;
        float4* dst = (float4*)(qw + a * 68 + qt * 16);
#pragma unroll
        for (int f = 0; f < 4; ++f) {
            float4 p = src[f], s = s4[f];
            dst[f] = make_float4(p.x + s.x, p.y + s.y, p.z + s.z, p.w + s.w);
        }
    }
    // ---- gather k = Pk[c] + Sk ----
    {
        int j = l >> 1, h = l & 1;
        const float4* src = (const float4*)(Pbase + (size_t)c[j] * RWS + 64 + h * 32);
        const float4* s4  = (const float4*)(Sp + 64 + h * 32);
        float4* dst = (float4*)(kw + j * 68 + h * 32);
#pragma unroll
        for (int f = 0; f < 8; ++f) {
            float4 p = src[f], s = s4[f];
            dst[f] = make_float4(p.x + s.x, p.y + s.y, p.z + s.z, p.w + s.w);
        }
    }
    __syncwarp();

    // ---- logits with packed f32x2 ----
    const int nq = l & 7, jg = l >> 3;
    u64 acc2[4] = {0ull, 0ull, 0ull, 0ull};
    const ulonglong2* qrow = (const ulonglong2*)(qw + nq * 68);
#pragma unroll
    for (int dc = 0; dc < 4; ++dc) {
        ulonglong2 qa = qrow[dc * 4 + 0], qb = qrow[dc * 4 + 1];
        ulonglong2 qc = qrow[dc * 4 + 2], qd = qrow[dc * 4 + 3];
#pragma unroll
        for (int j4 = 0; j4 < 4; ++j4) {
            const ulonglong2* kr = (const ulonglong2*)(kw + (j4 * 4 + jg) * 68);
            ulonglong2 ka = kr[dc * 4 + 0], kb = kr[dc * 4 + 1];
            ulonglong2 kc = kr[dc * 4 + 2], kd = kr[dc * 4 + 3];
            u64 s = acc2[j4];
            s = ffma2(qa.x, ka.x, s); s = ffma2(qa.y, ka.y, s);
            s = ffma2(qb.x, kb.x, s); s = ffma2(qb.y, kb.y, s);
            s = ffma2(qc.x, kc.x, s); s = ffma2(qc.y, kc.y, s);
            s = ffma2(qd.x, kd.x, s); s = ffma2(qd.y, kd.y, s);
            acc2[j4] = s;
        }
    }
    float acc[4];
#pragma unroll
    for (int j4 = 0; j4 < 4; ++j4) {
        float lo, hi; unpack2(acc2[j4], lo, hi);
        acc[j4] = lo + hi;
    }

    // ---- softmax over j per query row nq ----
    float mx = fmaxf(fmaxf(acc[0], acc[1]), fmaxf(acc[2], acc[3]));
    mx = fmaxf(mx, __shfl_xor_sync(0xffffffffu, mx, 8));
    mx = fmaxf(mx, __shfl_xor_sync(0xffffffffu, mx, 16));
    float e[4], ssum = 0.f;
#pragma unroll
    for (int j4 = 0; j4 < 4; ++j4) { e[j4] = __expf(acc[j4] - mx); ssum += e[j4]; }
    ssum += __shfl_xor_sync(0xffffffffu, ssum, 8);
    ssum += __shfl_xor_sync(0xffffffffu, ssum, 16);
    float inv = 1.0f / ssum;
    float wj[4];
#pragma unroll
    for (int j4 = 0; j4 < 4; ++j4) wj[j4] = e[j4] * inv;

    // ---- colsum over the 8 queries ----
#pragma unroll
    for (int off = 1; off < 8; off <<= 1)
#pragma unroll
        for (int j4 = 0; j4 < 4; ++j4)
            wj[j4] += __shfl_xor_sync(0xffffffffu, wj[j4], off);

    // ---- res128 = sum_j w[j]*PvProj[c_j] + wsum*SvProj (packed) ----
    u64 av0 = 0ull, av1 = 0ull;
#pragma unroll
    for (int j = 0; j < 16; ++j) {
        float wjv = __shfl_sync(0xffffffffu, wj[j >> 2], (j & 3) * 8);
        u64 w2 = dup2(wjv);
        ulonglong2 vv = *(const ulonglong2*)(Pbase + (size_t)c[j] * RWS + 128 + 4 * l);
        av0 = ffma2(w2, vv.x, av0);
        av1 = ffma2(w2, vv.y, av1);
    }
    float wsum = wj[0] + wj[1] + wj[2] + wj[3];
    wsum += __shfl_xor_sync(0xffffffffu, wsum, 8);
    wsum += __shfl_xor_sync(0xffffffffu, wsum, 16);
    {
        u64 w2 = dup2(wsum);
        ulonglong2 sv = *(const ulonglong2*)(Sp + 128 + 4 * l);
        av0 = ffma2(w2, sv.x, av0);
        av1 = ffma2(w2, sv.y, av1);
    }
    {
        float4 r;
        unpack2(av0, r.x, r.y);
        unpack2(av1, r.z, r.w);
        *(float4*)(resT + w * 132 + 4 * l) = r;
    }
    __syncthreads();

    // ---- out = res + b1 + feature ----
    const int o  = tid >> 1;
    const int pg = (tid & 1) * 4;
    const int gp0 = blockIdx.x * 8;
    const int bb = gp0 >> 12, nl = gp0 & (NN - 1);
    size_t base = ((size_t)bb * CC + o) * NN + nl + pg;
    float bo = b1[o];
    float4 fv = *(const float4*)(feature + base);
    float4 ov;
    ov.x = resT[(pg + 0) * 132 + o] + bo + fv.x;
    ov.y = resT[(pg + 1) * 132 + o] + bo + fv.y;
    ov.z = resT[(pg + 2) * 132 + o] + bo + fv.z;
    ov.w = resT[(pg + 3) * 132 + o] + bo + fv.w;
    *(float4*)(out + base) = ov;
}

// ---------------- launch ----------------
extern "C" void kernel_launch(void* const* d_in, const int* in_sizes, int n_in,
                              void* d_out, int out_size) {
    const float* feature = (const float*)d_in[0];
    const float* xyz     = (const float*)d_in[1];
    const float* wq      = (const float*)d_in[2];
    const float* bq      = (const float*)d_in[3];
    const float* wk      = (const float*)d_in[4];
    const float* bk      = (const float*)d_in[5];
    const float* wv      = (const float*)d_in[6];
    const float* bv      = (const float*)d_in[7];
    const float* w1      = (const float*)d_in[8];
    const float* b1      = (const float*)d_in[9];
    float* out = (float*)d_out;

    const int knn_smem  = NN * 16;
    const int attn_smem = SM_ATTN_TOT * 4;
    cudaFuncSetAttribute(knn_kernel,  cudaFuncAttributeMaxDynamicSharedMemorySize, knn_smem);
    cudaFuncSetAttribute(attn_kernel, cudaFuncAttributeMaxDynamicSharedMemorySize, attn_smem);

    {
        int total = KPAD * RWS + RWS;
        prep_kernel<<<(total + 255) / 256, 256>>>(wq, wk, wv, bq, bk, bv, w1);
    }
    knn_kernel<<<BB * 32, 128, knn_smem>>>(xyz);
    gemm_kernel<<<dim3(NPTS / 128, RWS / 128), 256>>>(xyz, feature);
    attn_kernel<<<NPTS / 8, 256, attn_smem>>>(feature, b1, out);
}

// round 6
// speedup vs baseline: 2.8620x; 2.0378x over previous
#include <cuda_runtime.h>
#include <math.h>

#define BB   4
#define NN   4096
#define CC   128
#define KK1  16
#define KK2  8
#define TDD  64
#define KDIM 131
#define KPAD 144
#define RWS  512
#define NPTS (BB*NN)

typedef unsigned long long u64;

__device__ __forceinline__ u64 ffma2(u64 a, u64 b, u64 c) {
    u64 d;
    asm("fma.rn.f32x2 %0, %1, %2, %3;" : "=l"(d) : "l"(a), "l"(b), "l"(c));
    return d;
}
__device__ __forceinline__ u64 dup2(float x) {
    u64 d;
    asm("mov.b64 %0, {%1, %1};" : "=l"(d) : "r"(__float_as_int(x)));
    return d;
}
__device__ __forceinline__ void unpack2(u64 v, float& lo, float& hi) {
    int a, b;
    asm("mov.b64 {%0, %1}, %2;" : "=r"(a), "=r"(b) : "l"(v));
    lo = __int_as_float(a); hi = __int_as_float(b);
}

// ---------------- scratch ----------------
__device__ int   g_idx[NPTS*KK1];
// per point rows: [0:64)Pq [64:128)Pk [128:256)PvProj [256:320)Sq [320:384)Sk [384:512)SvProj
__device__ float g_P[(size_t)NPTS*RWS];
__device__ float g_WcT[KPAD*RWS];
__device__ float g_bias[RWS];

// ---------------- prep ----------------
__global__ void prep_kernel(const float* __restrict__ wq, const float* __restrict__ wk,
                            const float* __restrict__ wv, const float* __restrict__ bq,
                            const float* __restrict__ bk, const float* __restrict__ bv,
                            const float* __restrict__ w1) {
    int i = blockIdx.x * blockDim.x + threadIdx.x;
    const int total1 = KPAD * RWS;
    if (i < total1) {
        int k = i >> 9;
        int r = i & 511;
        float val = 0.f;
        if (k < KDIM) {
            if (r < 128) {                       // Pq | Pk
                const float* w = (r < 64) ? wq : wk;
                const float* row = w + (r & 63) * 262;
                val = (k < 3) ? row[k] : row[6 + (k - 3)];
            } else if (r < 256) {                // PvProj = w1 @ Pv
                int o = r - 128;
                float s = 0.f;
                for (int m = 0; m < TDD; ++m) {
                    const float* row = wv + m * 262;
                    float wvk = (k < 3) ? row[k] : row[6 + (k - 3)];
                    s = fmaf(w1[o * TDD + m], wvk, s);
                }
                val = s;
            } else if (r < 384) {                // Sq | Sk
                const float* w = (r < 320) ? wq : wk;
                const float* row = w + (r & 63) * 262;
                val = (k < 3) ? (row[3 + k] - row[k])
                              : (row[134 + (k - 3)] - row[6 + (k - 3)]);
            } else {                             // SvProj = w1 @ Sv
                int o = r - 384;
                float s = 0.f;
                for (int m = 0; m < TDD; ++m) {
                    const float* row = wv + m * 262;
                    float d = (k < 3) ? (row[3 + k] - row[k])
                                      : (row[134 + (k - 3)] - row[6 + (k - 3)]);
                    s = fmaf(w1[o * TDD + m], d, s);
                }
                val = s;
            }
        }
        g_WcT[(k << 9) + r] = val;
        return;
    }
    i -= total1;
    if (i < RWS) {
        float bval = 0.f;
        if (i >= 256 && i < 320) bval = bq[i - 256];
        else if (i >= 320 && i < 384) bval = bk[i - 320];
        else if (i >= 384) {
            int o = i - 384;
            float s = 0.f;
            for (int m = 0; m < TDD; ++m) s = fmaf(w1[o * TDD + m], bv[m], s);
            bval = s;
        }
        g_bias[i] = bval;
    }
}

// ---------------- kNN: warp per query, distributed sorted top-16 list ----------------
// 16 warps/block = 16 queries/block; lane j evaluates candidate t*32+j each iter.
// List distributed: lane s holds rank-s (dist, idx); lanes 16-31 are shadow overflow.
__global__ __launch_bounds__(512) void knn_kernel(const float* __restrict__ xyz) {
    extern __shared__ float4 sh[];                 // 4096 * 16B = 64KB
    const unsigned FULL = 0xffffffffu;
    const int bi = blockIdx.x;
    const int b = bi >> 8;                         // 256 blocks per batch
    const int qbase = (bi & 255) * 16;
    const int tid = threadIdx.x;
    const int w = tid >> 5, lane = tid & 31;
    const float* xb = xyz + (size_t)b * 3 * NN;

    for (int i = tid; i < NN; i += 512) {
        float x = xb[i], y = xb[NN + i], z = xb[2 * NN + i];
        float sq = fmaf(z, z, fmaf(y, y, x * x));
        sh[i] = make_float4(x, y, z, sq);
    }
    __syncthreads();

    const int qlocal = qbase + w;
    const float4 q = sh[qlocal];
    const float INF = __int_as_float(0x7f800000);

    float dl = INF;            // my rank's distance
    int   il = 0;              // my rank's index
    float kth = INF;           // dl at rank 15 (warp-uniform)

    for (int t = 0; t < NN / 32; ++t) {
        const int m = t * 32 + lane;
        float4 c = sh[m];
        float dot = q.x * c.x;
        dot = fmaf(q.y, c.y, dot);
        dot = fmaf(q.z, c.z, dot);
        float d = fmaf(-2.0f, dot, c.w);       // c.w - 2 q.c (q.w const/query: dropped)
        if (m == qlocal) d = INF;

        unsigned mask = __ballot_sync(FULL, d < kth);
        if (mask) {
            do {
                const int src = __ffs(mask) - 1;
                mask &= mask - 1;
                const float dc = __shfl_sync(FULL, d, src);
                const int   mc = t * 32 + src;
                const float up_d = __shfl_up_sync(FULL, dl, 1);
                const int   up_i = __shfl_up_sync(FULL, il, 1);
                const bool here = dc < dl;                  // strict: stable tie-break
                const bool prev = (lane > 0) && (dc < up_d);
                dl = here ? (prev ? up_d : dc) : dl;
                il = here ? (prev ? up_i : mc) : il;
            } while (mask);
            kth = __shfl_sync(FULL, dl, 15);
        }
    }

    if (lane < KK1) {
        g_idx[((size_t)b * NN + qlocal) * KK1 + lane] = il;
    }
}

// ---------------- SGEMM with packed f32x2 FMA ----------------
__global__ __launch_bounds__(256, 2) void gemm_kernel(const float* __restrict__ xyz,
                                                      const float* __restrict__ feature) {
    __shared__ __align__(16) float As[16][128];
    __shared__ __align__(16) float Bs[16][128];

    const int tid = threadIdx.x;
    const int tr = tid >> 4;
    const int tc = tid & 15;
    const int p0 = blockIdx.x * 128;
    const int b  = p0 >> 12;
    const int nl = p0 & (NN - 1);
    const int rowbase = blockIdx.y * 128;

    const int la_k = tid >> 4;
    const int la_r = (tid & 15) * 8;
    const int lb_k = tid >> 4;
    const int lb_j = (tid & 15) * 8;

    u64 acc[8][4];
#pragma unroll
    for (int i = 0; i < 8; ++i)
#pragma unroll
        for (int j = 0; j < 4; ++j) acc[i][j] = 0ull;

    float4 pa0, pa1, pb0, pb1;
    {
        const float* srcA = g_WcT + la_k * RWS + rowbase + la_r;
        pa0 = *(const float4*)srcA; pa1 = *(const float4*)(srcA + 4);
        int kg = lb_k;
        const float* row = (kg < 3) ? (xyz + ((size_t)b * 3 + kg) * NN)
                                    : (feature + ((size_t)b * CC + (kg - 3)) * NN);
        pb0 = *(const float4*)(row + nl + lb_j);
        pb1 = *(const float4*)(row + nl + lb_j + 4);
    }

    for (int kt = 0; kt < KPAD / 16; ++kt) {
        *(float4*)&As[la_k][la_r]     = pa0;
        *(float4*)&As[la_k][la_r + 4] = pa1;
        *(float4*)&Bs[lb_k][lb_j]     = pb0;
        *(float4*)&Bs[lb_k][lb_j + 4] = pb1;
        __syncthreads();
        if (kt + 1 < KPAD / 16) {
            const float* srcA = g_WcT + ((kt + 1) * 16 + la_k) * RWS + rowbase + la_r;
            pa0 = *(const float4*)srcA; pa1 = *(const float4*)(srcA + 4);
            int kg = (kt + 1) * 16 + lb_k;
            if (kg < KDIM) {
                const float* row = (kg < 3) ? (xyz + ((size_t)b * 3 + kg) * NN)
                                            : (feature + ((size_t)b * CC + (kg - 3)) * NN);
                pb0 = *(const float4*)(row + nl + lb_j);
                pb1 = *(const float4*)(row + nl + lb_j + 4);
            } else {
                pb0 = make_float4(0.f, 0.f, 0.f, 0.f);
                pb1 = pb0;
            }
        }
#pragma unroll
        for (int k = 0; k < 16; ++k) {
            float4 a0 = *(const float4*)&As[k][tr * 8];
            float4 a1 = *(const float4*)&As[k][tr * 8 + 4];
            ulonglong2 b0 = *(const ulonglong2*)&Bs[k][tc * 8];
            ulonglong2 b1 = *(const ulonglong2*)&Bs[k][tc * 8 + 4];
            u64 bp[4] = {b0.x, b0.y, b1.x, b1.y};
            float ar[8] = {a0.x, a0.y, a0.z, a0.w, a1.x, a1.y, a1.z, a1.w};
#pragma unroll
            for (int i = 0; i < 8; ++i) {
                u64 a2 = dup2(ar[i]);
#pragma unroll
                for (int j = 0; j < 4; ++j)
                    acc[i][j] = ffma2(a2, bp[j], acc[i][j]);
            }
        }
        __syncthreads();
    }

    const int gr = rowbase + tr * 8;
    float bias[8];
#pragma unroll
    for (int i = 0; i < 8; ++i) bias[i] = g_bias[gr + i];
    float r_[8][8];
#pragma unroll
    for (int i = 0; i < 8; ++i)
#pragma unroll
        for (int j = 0; j < 4; ++j)
            unpack2(acc[i][j], r_[i][2 * j], r_[i][2 * j + 1]);
#pragma unroll
    for (int j = 0; j < 8; ++j) {
        int p = p0 + tc * 8 + j;
        float* dst = g_P + (size_t)p * RWS + gr;
        float4 v0 = make_float4(r_[0][j] + bias[0], r_[1][j] + bias[1],
                                r_[2][j] + bias[2], r_[3][j] + bias[3]);
        float4 v1 = make_float4(r_[4][j] + bias[4], r_[5][j] + bias[5],
                                r_[6][j] + bias[6], r_[7][j] + bias[7]);
        *(float4*)dst       = v0;
        *(float4*)(dst + 4) = v1;
    }
}

// ---------------- attention ----------------
#define WARP_FLOATS 1632
#define SM_RES      (8*WARP_FLOATS)
#define SM_ATTN_TOT (SM_RES + 8*132)

__global__ __launch_bounds__(256, 3) void attn_kernel(const float* __restrict__ feature,
                                                      const float* __restrict__ b1,
                                                      float* __restrict__ out) {
    extern __shared__ __align__(16) float sm[];
    const int tid = threadIdx.x;
    const int w = tid >> 5, l = tid & 31;
    float* qw   = sm + w * WARP_FLOATS;
    float* kw   = qw + 8 * 68;
    float* resT = sm + SM_RES;

    const int gp = blockIdx.x * 8 + w;
    const int b  = gp >> 12;
    const int* ip = g_idx + (size_t)gp * KK1;
    const float* Pbase = g_P + ((size_t)(b << 12)) * RWS;
    const float* Sp    = g_P + (size_t)gp * RWS + 256;

    int c[16];
    {
        int4 t0 = ((const int4*)ip)[0]; int4 t1 = ((const int4*)ip)[1];
        int4 t2 = ((const int4*)ip)[2]; int4 t3 = ((const int4*)ip)[3];
        c[0]=t0.x; c[1]=t0.y; c[2]=t0.z; c[3]=t0.w;
        c[4]=t1.x; c[5]=t1.y; c[6]=t1.z; c[7]=t1.w;
        c[8]=t2.x; c[9]=t2.y; c[10]=t2.z; c[11]=t2.w;
        c[12]=t3.x; c[13]=t3.y; c[14]=t3.z; c[15]=t3.w;
    }

    // ---- gather q = Pq[c] + Sq ----
    {
        int a = l >> 2, qt = l & 3;
        const float4* src = (const float4*)(Pbase + (size_t)c[a] * RWS) + qt * 4;
        const float4* s4  = (const float4*)Sp + qt * 4;
        float4* dst = (float4*)(qw + a * 68 + qt * 16);
#pragma unroll
        for (int f = 0; f < 4; ++f) {
            float4 p = src[f], s = s4[f];
            dst[f] = make_float4(p.x + s.x, p.y + s.y, p.z + s.z, p.w + s.w);
        }
    }
    // ---- gather k = Pk[c] + Sk ----
    {
        int j = l >> 1, h = l & 1;
        const float4* src = (const float4*)(Pbase + (size_t)c[j] * RWS + 64 + h * 32);
        const float4* s4  = (const float4*)(Sp + 64 + h * 32);
        float4* dst = (float4*)(kw + j * 68 + h * 32);
#pragma unroll
        for (int f = 0; f < 8; ++f) {
            float4 p = src[f], s = s4[f];
            dst[f] = make_float4(p.x + s.x, p.y + s.y, p.z + s.z, p.w + s.w);
        }
    }
    __syncwarp();

    // ---- logits with packed f32x2 ----
    const int nq = l & 7, jg = l >> 3;
    u64 acc2[4] = {0ull, 0ull, 0ull, 0ull};
    const ulonglong2* qrow = (const ulonglong2*)(qw + nq * 68);
#pragma unroll
    for (int dc = 0; dc < 4; ++dc) {
        ulonglong2 qa = qrow[dc * 4 + 0], qb = qrow[dc * 4 + 1];
        ulonglong2 qc = qrow[dc * 4 + 2], qd = qrow[dc * 4 + 3];
#pragma unroll
        for (int j4 = 0; j4 < 4; ++j4) {
            const ulonglong2* kr = (const ulonglong2*)(kw + (j4 * 4 + jg) * 68);
            ulonglong2 ka = kr[dc * 4 + 0], kb = kr[dc * 4 + 1];
            ulonglong2 kc = kr[dc * 4 + 2], kd = kr[dc * 4 + 3];
            u64 s = acc2[j4];
            s = ffma2(qa.x, ka.x, s); s = ffma2(qa.y, ka.y, s);
            s = ffma2(qb.x, kb.x, s); s = ffma2(qb.y, kb.y, s);
            s = ffma2(qc.x, kc.x, s); s = ffma2(qc.y, kc.y, s);
            s = ffma2(qd.x, kd.x, s); s = ffma2(qd.y, kd.y, s);
            acc2[j4] = s;
        }
    }
    float acc[4];
#pragma unroll
    for (int j4 = 0; j4 < 4; ++j4) {
        float lo, hi; unpack2(acc2[j4], lo, hi);
        acc[j4] = lo + hi;
    }

    // ---- softmax over j per query row nq ----
    float mx = fmaxf(fmaxf(acc[0], acc[1]), fmaxf(acc[2], acc[3]));
    mx = fmaxf(mx, __shfl_xor_sync(0xffffffffu, mx, 8));
    mx = fmaxf(mx, __shfl_xor_sync(0xffffffffu, mx, 16));
    float e[4], ssum = 0.f;
#pragma unroll
    for (int j4 = 0; j4 < 4; ++j4) { e[j4] = __expf(acc[j4] - mx); ssum += e[j4]; }
    ssum += __shfl_xor_sync(0xffffffffu, ssum, 8);
    ssum += __shfl_xor_sync(0xffffffffu, ssum, 16);
    float inv = 1.0f / ssum;
    float wj[4];
#pragma unroll
    for (int j4 = 0; j4 < 4; ++j4) wj[j4] = e[j4] * inv;

    // ---- colsum over the 8 queries ----
#pragma unroll
    for (int off = 1; off < 8; off <<= 1)
#pragma unroll
        for (int j4 = 0; j4 < 4; ++j4)
            wj[j4] += __shfl_xor_sync(0xffffffffu, wj[j4], off);

    // ---- res128 = sum_j w[j]*PvProj[c_j] + wsum*SvProj (packed) ----
    u64 av0 = 0ull, av1 = 0ull;
#pragma unroll
    for (int j = 0; j < 16; ++j) {
        float wjv = __shfl_sync(0xffffffffu, wj[j >> 2], (j & 3) * 8);
        u64 w2 = dup2(wjv);
        ulonglong2 vv = *(const ulonglong2*)(Pbase + (size_t)c[j] * RWS + 128 + 4 * l);
        av0 = ffma2(w2, vv.x, av0);
        av1 = ffma2(w2, vv.y, av1);
    }
    float wsum = wj[0] + wj[1] + wj[2] + wj[3];
    wsum += __shfl_xor_sync(0xffffffffu, wsum, 8);
    wsum += __shfl_xor_sync(0xffffffffu, wsum, 16);
    {
        u64 w2 = dup2(wsum);
        ulonglong2 sv = *(const ulonglong2*)(Sp + 128 + 4 * l);
        av0 = ffma2(w2, sv.x, av0);
        av1 = ffma2(w2, sv.y, av1);
    }
    {
        float4 r;
        unpack2(av0, r.x, r.y);
        unpack2(av1, r.z, r.w);
        *(float4*)(resT + w * 132 + 4 * l) = r;
    }
    __syncthreads();

    // ---- out = res + b1 + feature ----
    const int o  = tid >> 1;
    const int pg = (tid & 1) * 4;
    const int gp0 = blockIdx.x * 8;
    const int bb = gp0 >> 12, nl = gp0 & (NN - 1);
    size_t base = ((size_t)bb * CC + o) * NN + nl + pg;
    float bo = b1[o];
    float4 fv = *(const float4*)(feature + base);
    float4 ov;
    ov.x = resT[(pg + 0) * 132 + o] + bo + fv.x;
    ov.y = resT[(pg + 1) * 132 + o] + bo + fv.y;
    ov.z = resT[(pg + 2) * 132 + o] + bo + fv.z;
    ov.w = resT[(pg + 3) * 132 + o] + bo + fv.w;
    *(float4*)(out + base) = ov;
}

// ---------------- launch ----------------
extern "C" void kernel_launch(void* const* d_in, const int* in_sizes, int n_in,
                              void* d_out, int out_size) {
    const float* feature = (const float*)d_in[0];
    const float* xyz     = (const float*)d_in[1];
    const float* wq      = (const float*)d_in[2];
    const float* bq      = (const float*)d_in[3];
    const float* wk      = (const float*)d_in[4];
    const float* bk      = (const float*)d_in[5];
    const float* wv      = (const float*)d_in[6];
    const float* bv      = (const float*)d_in[7];
    const float* w1      = (const float*)d_in[8];
    const float* b1      = (const float*)d_in[9];
    float* out = (float*)d_out;

    const int knn_smem  = NN * 16;
    const int attn_smem = SM_ATTN_TOT * 4;
    cudaFuncSetAttribute(knn_kernel,  cudaFuncAttributeMaxDynamicSharedMemorySize, knn_smem);
    cudaFuncSetAttribute(attn_kernel, cudaFuncAttributeMaxDynamicSharedMemorySize, attn_smem);

    {
        int total = KPAD * RWS + RWS;
        prep_kernel<<<(total + 255) / 256, 256>>>(wq, wk, wv, bq, bk, bv, w1);
    }
    knn_kernel<<<BB * 256, 512, knn_smem>>>(xyz);
    gemm_kernel<<<dim3(NPTS / 128, RWS / 128), 256>>>(xyz, feature);
    attn_kernel<<<NPTS / 8, 256, attn_smem>>>(feature, b1, out);
}

// round 7
// speedup vs baseline: 3.0459x; 1.0643x over previous
#include <cuda_runtime.h>
#include <math.h>

#define BB   4
#define NN   4096
#define CC   128
#define KK1  16
#define KK2  8
#define TDD  64
#define KDIM 131
#define KPAD 144
#define RWS  512
#define NPTS (BB*NN)

typedef unsigned long long u64;

__device__ __forceinline__ u64 ffma2(u64 a, u64 b, u64 c) {
    u64 d;
    asm("fma.rn.f32x2 %0, %1, %2, %3;" : "=l"(d) : "l"(a), "l"(b), "l"(c));
    return d;
}
__device__ __forceinline__ u64 dup2(float x) {
    u64 d;
    asm("mov.b64 %0, {%1, %1};" : "=l"(d) : "r"(__float_as_int(x)));
    return d;
}
__device__ __forceinline__ void unpack2(u64 v, float& lo, float& hi) {
    int a, b;
    asm("mov.b64 {%0, %1}, %2;" : "=r"(a), "=r"(b) : "l"(v));
    lo = __int_as_float(a); hi = __int_as_float(b);
}

// ---------------- scratch ----------------
__device__ int   g_idx[NPTS*KK1];
// per point rows: [0:64)Pq [64:128)Pk [128:256)PvProj [256:320)Sq [320:384)Sk [384:512)SvProj
__device__ float g_P[(size_t)NPTS*RWS];
__device__ float g_WcT[KPAD*RWS];
__device__ float g_bias[RWS];

// ---------------- prep ----------------
__global__ void prep_kernel(const float* __restrict__ wq, const float* __restrict__ wk,
                            const float* __restrict__ wv, const float* __restrict__ bq,
                            const float* __restrict__ bk, const float* __restrict__ bv,
                            const float* __restrict__ w1) {
    int i = blockIdx.x * blockDim.x + threadIdx.x;
    const int total1 = KPAD * RWS;
    if (i < total1) {
        int k = i >> 9;
        int r = i & 511;
        float val = 0.f;
        if (k < KDIM) {
            if (r < 128) {                       // Pq | Pk
                const float* w = (r < 64) ? wq : wk;
                const float* row = w + (r & 63) * 262;
                val = (k < 3) ? row[k] : row[6 + (k - 3)];
            } else if (r < 256) {                // PvProj = w1 @ Pv
                int o = r - 128;
                float s = 0.f;
                for (int m = 0; m < TDD; ++m) {
                    const float* row = wv + m * 262;
                    float wvk = (k < 3) ? row[k] : row[6 + (k - 3)];
                    s = fmaf(w1[o * TDD + m], wvk, s);
                }
                val = s;
            } else if (r < 384) {                // Sq | Sk
                const float* w = (r < 320) ? wq : wk;
                const float* row = w + (r & 63) * 262;
                val = (k < 3) ? (row[3 + k] - row[k])
                              : (row[134 + (k - 3)] - row[6 + (k - 3)]);
            } else {                             // SvProj = w1 @ Sv
                int o = r - 384;
                float s = 0.f;
                for (int m = 0; m < TDD; ++m) {
                    const float* row = wv + m * 262;
                    float d = (k < 3) ? (row[3 + k] - row[k])
                                      : (row[134 + (k - 3)] - row[6 + (k - 3)]);
                    s = fmaf(w1[o * TDD + m], d, s);
                }
                val = s;
            }
        }
        g_WcT[(k << 9) + r] = val;
        return;
    }
    i -= total1;
    if (i < RWS) {
        float bval = 0.f;
        if (i >= 256 && i < 320) bval = bq[i - 256];
        else if (i >= 320 && i < 384) bval = bk[i - 320];
        else if (i >= 384) {
            int o = i - 384;
            float s = 0.f;
            for (int m = 0; m < TDD; ++m) s = fmaf(w1[o * TDD + m], bv[m], s);
            bval = s;
        }
        g_bias[i] = bval;
    }
}

// ---------------- kNN: warp per query, distributed sorted top-16 list ----------------
// Init: bitonic-sort first 32 candidates across lanes (lane = rank).
// Loop: ballot hits vs kth, shuffle-shift insert (stable lower-index-first ties).
__global__ __launch_bounds__(512) void knn_kernel(const float* __restrict__ xyz) {
    extern __shared__ float4 sh[];                 // 4096 * 16B = 64KB
    const unsigned FULL = 0xffffffffu;
    const int bi = blockIdx.x;
    const int b = bi >> 8;                         // 256 blocks per batch
    const int qbase = (bi & 255) * 16;
    const int tid = threadIdx.x;
    const int w = tid >> 5, lane = tid & 31;
    const float* xb = xyz + (size_t)b * 3 * NN;

    for (int i = tid; i < NN; i += 512) {
        float x = xb[i], y = xb[NN + i], z = xb[2 * NN + i];
        float sq = fmaf(z, z, fmaf(y, y, x * x));
        sh[i] = make_float4(x, y, z, sq);
    }
    __syncthreads();

    const int qlocal = qbase + w;
    const float4 q = sh[qlocal];
    const float INF = __int_as_float(0x7f800000);

    // ---- t = 0: evaluate first 32 candidates, bitonic sort across lanes ----
    float dl;
    int   il = lane;
    {
        float4 c = sh[lane];
        float dot = q.x * c.x;
        dot = fmaf(q.y, c.y, dot);
        dot = fmaf(q.z, c.z, dot);
        dl = fmaf(-2.0f, dot, c.w);
        if (lane == qlocal) dl = INF;
    }
#pragma unroll
    for (int k = 2; k <= 32; k <<= 1) {
#pragma unroll
        for (int j = k >> 1; j > 0; j >>= 1) {
            float od = __shfl_xor_sync(FULL, dl, j);
            int   oi = __shfl_xor_sync(FULL, il, j);
            bool lower = (lane & j) == 0;
            bool asc   = (lane & k) == 0;
            bool lt = (od < dl) || (od == dl && oi < il);   // other strictly before mine
            bool sw = asc ? (lower ? lt : !lt) : (lower ? !lt : lt);
            if (sw) { dl = od; il = oi; }
        }
    }
    float kth = __shfl_sync(FULL, dl, 15);

    // ---- main scan ----
    for (int t = 1; t < NN / 32; ++t) {
        const int m = t * 32 + lane;
        float4 c = sh[m];
        float dot = q.x * c.x;
        dot = fmaf(q.y, c.y, dot);
        dot = fmaf(q.z, c.z, dot);
        float d = fmaf(-2.0f, dot, c.w);       // c.w - 2 q.c (q.w const/query: dropped)
        if (m == qlocal) d = INF;

        unsigned mask = __ballot_sync(FULL, d < kth);
        if (mask) {
            do {
                const int src = __ffs(mask) - 1;
                mask &= mask - 1;
                const float dc = __shfl_sync(FULL, d, src);
                const int   mc = t * 32 + src;
                const float up_d = __shfl_up_sync(FULL, dl, 1);
                const int   up_i = __shfl_up_sync(FULL, il, 1);
                const bool here = dc < dl;                  // strict: stable tie-break
                const bool prev = (lane > 0) && (dc < up_d);
                dl = here ? (prev ? up_d : dc) : dl;
                il = here ? (prev ? up_i : mc) : il;
            } while (mask);
            kth = __shfl_sync(FULL, dl, 15);
        }
    }

    if (lane < KK1) {
        g_idx[((size_t)b * NN + qlocal) * KK1 + lane] = il;
    }
}

// ---------------- SGEMM with packed f32x2 FMA ----------------
__global__ __launch_bounds__(256, 2) void gemm_kernel(const float* __restrict__ xyz,
                                                      const float* __restrict__ feature) {
    __shared__ __align__(16) float As[16][128];
    __shared__ __align__(16) float Bs[16][128];

    const int tid = threadIdx.x;
    const int tr = tid >> 4;
    const int tc = tid & 15;
    const int p0 = blockIdx.x * 128;
    const int b  = p0 >> 12;
    const int nl = p0 & (NN - 1);
    const int rowbase = blockIdx.y * 128;

    const int la_k = tid >> 4;
    const int la_r = (tid & 15) * 8;
    const int lb_k = tid >> 4;
    const int lb_j = (tid & 15) * 8;

    u64 acc[8][4];
#pragma unroll
    for (int i = 0; i < 8; ++i)
#pragma unroll
        for (int j = 0; j < 4; ++j) acc[i][j] = 0ull;

    float4 pa0, pa1, pb0, pb1;
    {
        const float* srcA = g_WcT + la_k * RWS + rowbase + la_r;
        pa0 = *(const float4*)srcA; pa1 = *(const float4*)(srcA + 4);
        int kg = lb_k;
        const float* row = (kg < 3) ? (xyz + ((size_t)b * 3 + kg) * NN)
                                    : (feature + ((size_t)b * CC + (kg - 3)) * NN);
        pb0 = *(const float4*)(row + nl + lb_j);
        pb1 = *(const float4*)(row + nl + lb_j + 4);
    }

    for (int kt = 0; kt < KPAD / 16; ++kt) {
        *(float4*)&As[la_k][la_r]     = pa0;
        *(float4*)&As[la_k][la_r + 4] = pa1;
        *(float4*)&Bs[lb_k][lb_j]     = pb0;
        *(float4*)&Bs[lb_k][lb_j + 4] = pb1;
        __syncthreads();
        if (kt + 1 < KPAD / 16) {
            const float* srcA = g_WcT + ((kt + 1) * 16 + la_k) * RWS + rowbase + la_r;
            pa0 = *(const float4*)srcA; pa1 = *(const float4*)(srcA + 4);
            int kg = (kt + 1) * 16 + lb_k;
            if (kg < KDIM) {
                const float* row = (kg < 3) ? (xyz + ((size_t)b * 3 + kg) * NN)
                                            : (feature + ((size_t)b * CC + (kg - 3)) * NN);
                pb0 = *(const float4*)(row + nl + lb_j);
                pb1 = *(const float4*)(row + nl + lb_j + 4);
            } else {
                pb0 = make_float4(0.f, 0.f, 0.f, 0.f);
                pb1 = pb0;
            }
        }
#pragma unroll
        for (int k = 0; k < 16; ++k) {
            float4 a0 = *(const float4*)&As[k][tr * 8];
            float4 a1 = *(const float4*)&As[k][tr * 8 + 4];
            ulonglong2 b0 = *(const ulonglong2*)&Bs[k][tc * 8];
            ulonglong2 b1 = *(const ulonglong2*)&Bs[k][tc * 8 + 4];
            u64 bp[4] = {b0.x, b0.y, b1.x, b1.y};
            float ar[8] = {a0.x, a0.y, a0.z, a0.w, a1.x, a1.y, a1.z, a1.w};
#pragma unroll
            for (int i = 0; i < 8; ++i) {
                u64 a2 = dup2(ar[i]);
#pragma unroll
                for (int j = 0; j < 4; ++j)
                    acc[i][j] = ffma2(a2, bp[j], acc[i][j]);
            }
        }
        __syncthreads();
    }

    const int gr = rowbase + tr * 8;
    float bias[8];
#pragma unroll
    for (int i = 0; i < 8; ++i) bias[i] = g_bias[gr + i];
    float r_[8][8];
#pragma unroll
    for (int i = 0; i < 8; ++i)
#pragma unroll
        for (int j = 0; j < 4; ++j)
            unpack2(acc[i][j], r_[i][2 * j], r_[i][2 * j + 1]);
#pragma unroll
    for (int j = 0; j < 8; ++j) {
        int p = p0 + tc * 8 + j;
        float* dst = g_P + (size_t)p * RWS + gr;
        float4 v0 = make_float4(r_[0][j] + bias[0], r_[1][j] + bias[1],
                                r_[2][j] + bias[2], r_[3][j] + bias[3]);
        float4 v1 = make_float4(r_[4][j] + bias[4], r_[5][j] + bias[5],
                                r_[6][j] + bias[6], r_[7][j] + bias[7]);
        *(float4*)dst       = v0;
        *(float4*)(dst + 4) = v1;
    }
}

// ---------------- attention ----------------
#define WARP_FLOATS 1632
#define SM_RES      (8*WARP_FLOATS)
#define SM_ATTN_TOT (SM_RES + 8*132)

__global__ __launch_bounds__(256, 3) void attn_kernel(const float* __restrict__ feature,
                                                      const float* __restrict__ b1,
                                                      float* __restrict__ out) {
    extern __shared__ __align__(16) float sm[];
    const int tid = threadIdx.x;
    const int w = tid >> 5, l = tid & 31;
    float* qw   = sm + w * WARP_FLOATS;
    float* kw   = qw + 8 * 68;
    float* resT = sm + SM_RES;

    const int gp = blockIdx.x * 8 + w;
    const int b  = gp >> 12;
    const int* ip = g_idx + (size_t)gp * KK1;
    const float* Pbase = g_P + ((size_t)(b << 12)) * RWS;
    const float* Sp    = g_P + (size_t)gp * RWS + 256;

    int c[16];
    {
        int4 t0 = ((const int4*)ip)[0]; int4 t1 = ((const int4*)ip)[1];
        int4 t2 = ((const int4*)ip)[2]; int4 t3 = ((const int4*)ip)[3];
        c[0]=t0.x; c[1]=t0.y; c[2]=t0.z; c[3]=t0.w;
        c[4]=t1.x; c[5]=t1.y; c[6]=t1.z; c[7]=t1.w;
        c[8]=t2.x; c[9]=t2.y; c[10]=t2.z; c[11]=t2.w;
        c[12]=t3.x; c[13]=t3.y; c[14]=t3.z; c[15]=t3.w;
    }

    // ---- gather q = Pq[c] + Sq ----
    {
        int a = l >> 2, qt = l & 3;
        const float4* src = (const float4*)(Pbase + (size_t)c[a] * RWS) + qt * 4;
        const float4* s4  = (const float4*)Sp + qt * 4;
        float4* dst = (float4*)(qw + a * 68 + qt * 16);
#pragma unroll
        for (int f = 0; f < 4; ++f) {
            float4 p = src[f], s = s4[f];
            dst[f] = make_float4(p.x + s.x, p.y + s.y, p.z + s.z, p.w + s.w);
        }
    }
    // ---- gather k = Pk[c] + Sk ----
    {
        int j = l >> 1, h = l & 1;
        const float4* src = (const float4*)(Pbase + (size_t)c[j] * RWS + 64 + h * 32);
        const float4* s4  = (const float4*)(Sp + 64 + h * 32);
        float4* dst = (float4*)(kw + j * 68 + h * 32);
#pragma unroll
        for (int f = 0; f < 8; ++f) {
            float4 p = src[f], s = s4[f];
            dst[f] = make_float4(p.x + s.x, p.y + s.y, p.z + s.z, p.w + s.w);
        }
    }
    __syncwarp();

    // ---- logits with packed f32x2 ----
    const int nq = l & 7, jg = l >> 3;
    u64 acc2[4] = {0ull, 0ull, 0ull, 0ull};
    const ulonglong2* qrow = (const ulonglong2*)(qw + nq * 68);
#pragma unroll
    for (int dc = 0; dc < 4; ++dc) {
        ulonglong2 qa = qrow[dc * 4 + 0], qb = qrow[dc * 4 + 1];
        ulonglong2 qc = qrow[dc * 4 + 2], qd = qrow[dc * 4 + 3];
#pragma unroll
        for (int j4 = 0; j4 < 4; ++j4) {
            const ulonglong2* kr = (const ulonglong2*)(kw + (j4 * 4 + jg) * 68);
            ulonglong2 ka = kr[dc * 4 + 0], kb = kr[dc * 4 + 1];
            ulonglong2 kc = kr[dc * 4 + 2], kd = kr[dc * 4 + 3];
            u64 s = acc2[j4];
            s = ffma2(qa.x, ka.x, s); s = ffma2(qa.y, ka.y, s);
            s = ffma2(qb.x, kb.x, s); s = ffma2(qb.y, kb.y, s);
            s = ffma2(qc.x, kc.x, s); s = ffma2(qc.y, kc.y, s);
            s = ffma2(qd.x, kd.x, s); s = ffma2(qd.y, kd.y, s);
            acc2[j4] = s;
        }
    }
    float acc[4];
#pragma unroll
    for (int j4 = 0; j4 < 4; ++j4) {
        float lo, hi; unpack2(acc2[j4], lo, hi);
        acc[j4] = lo + hi;
    }

    // ---- softmax over j per query row nq ----
    float mx = fmaxf(fmaxf(acc[0], acc[1]), fmaxf(acc[2], acc[3]));
    mx = fmaxf(mx, __shfl_xor_sync(0xffffffffu, mx, 8));
    mx = fmaxf(mx, __shfl_xor_sync(0xffffffffu, mx, 16));
    float e[4], ssum = 0.f;
#pragma unroll
    for (int j4 = 0; j4 < 4; ++j4) { e[j4] = __expf(acc[j4] - mx); ssum += e[j4]; }
    ssum += __shfl_xor_sync(0xffffffffu, ssum, 8);
    ssum += __shfl_xor_sync(0xffffffffu, ssum, 16);
    float inv = 1.0f / ssum;
    float wj[4];
#pragma unroll
    for (int j4 = 0; j4 < 4; ++j4) wj[j4] = e[j4] * inv;

    // ---- colsum over the 8 queries ----
#pragma unroll
    for (int off = 1; off < 8; off <<= 1)
#pragma unroll
        for (int j4 = 0; j4 < 4; ++j4)
            wj[j4] += __shfl_xor_sync(0xffffffffu, wj[j4], off);

    // ---- res128 = sum_j w[j]*PvProj[c_j] + wsum*SvProj (packed) ----
    u64 av0 = 0ull, av1 = 0ull;
#pragma unroll
    for (int j = 0; j < 16; ++j) {
        float wjv = __shfl_sync(0xffffffffu, wj[j >> 2], (j & 3) * 8);
        u64 w2 = dup2(wjv);
        ulonglong2 vv = *(const ulonglong2*)(Pbase + (size_t)c[j] * RWS + 128 + 4 * l);
        av0 = ffma2(w2, vv.x, av0);
        av1 = ffma2(w2, vv.y, av1);
    }
    float wsum = wj[0] + wj[1] + wj[2] + wj[3];
    wsum += __shfl_xor_sync(0xffffffffu, wsum, 8);
    wsum += __shfl_xor_sync(0xffffffffu, wsum, 16);
    {
        u64 w2 = dup2(wsum);
        ulonglong2 sv = *(const ulonglong2*)(Sp + 128 + 4 * l);
        av0 = ffma2(w2, sv.x, av0);
        av1 = ffma2(w2, sv.y, av1);
    }
    {
        float4 r;
        unpack2(av0, r.x, r.y);
        unpack2(av1, r.z, r.w);
        *(float4*)(resT + w * 132 + 4 * l) = r;
    }
    __syncthreads();

    // ---- out = res + b1 + feature ----
    const int o  = tid >> 1;
    const int pg = (tid & 1) * 4;
    const int gp0 = blockIdx.x * 8;
    const int bb = gp0 >> 12, nl = gp0 & (NN - 1);
    size_t base = ((size_t)bb * CC + o) * NN + nl + pg;
    float bo = b1[o];
    float4 fv = *(const float4*)(feature + base);
    float4 ov;
    ov.x = resT[(pg + 0) * 132 + o] + bo + fv.x;
    ov.y = resT[(pg + 1) * 132 + o] + bo + fv.y;
    ov.z = resT[(pg + 2) * 132 + o] + bo + fv.z;
    ov.w = resT[(pg + 3) * 132 + o] + bo + fv.w;
    *(float4*)(out + base) = ov;
}

// ---------------- launch: fork(knn || prep->gemm) -> join -> attn ----------------
extern "C" void kernel_launch(void* const* d_in, const int* in_sizes, int n_in,
                              void* d_out, int out_size) {
    const float* feature = (const float*)d_in[0];
    const float* xyz     = (const float*)d_in[1];
    const float* wq      = (const float*)d_in[2];
    const float* bq      = (const float*)d_in[3];
    const float* wk      = (const float*)d_in[4];
    const float* bk      = (const float*)d_in[5];
    const float* wv      = (const float*)d_in[6];
    const float* bv      = (const float*)d_in[7];
    const float* w1      = (const float*)d_in[8];
    const float* b1      = (const float*)d_in[9];
    float* out = (float*)d_out;

    // created once on the (uncaptured) correctness call; reused identically afterwards
    static cudaStream_t s_aux = []{
        cudaStream_t s; cudaStreamCreateWithFlags(&s, cudaStreamNonBlocking); return s; }();
    static cudaEvent_t ev_fork = []{
        cudaEvent_t e; cudaEventCreateWithFlags(&e, cudaEventDisableTiming); return e; }();
    static cudaEvent_t ev_join = []{
        cudaEvent_t e; cudaEventCreateWithFlags(&e, cudaEventDisableTiming); return e; }();
    static bool attr_done = []{
        cudaFuncSetAttribute(knn_kernel,  cudaFuncAttributeMaxDynamicSharedMemorySize, NN * 16);
        cudaFuncSetAttribute(attn_kernel, cudaFuncAttributeMaxDynamicSharedMemorySize, SM_ATTN_TOT * 4);
        return true; }();
    (void)attr_done;

    const int knn_smem  = NN * 16;
    const int attn_smem = SM_ATTN_TOT * 4;

    // fork
    cudaEventRecord(ev_fork, 0);
    cudaStreamWaitEvent(s_aux, ev_fork, 0);

    // aux branch: prep -> gemm
    {
        int total = KPAD * RWS + RWS;
        prep_kernel<<<(total + 255) / 256, 256, 0, s_aux>>>(wq, wk, wv, bq, bk, bv, w1);
    }
    gemm_kernel<<<dim3(NPTS / 128, RWS / 128), 256, 0, s_aux>>>(xyz, feature);

    // main branch: knn
    knn_kernel<<<BB * 256, 512, knn_smem>>>(xyz);

    // join
    cudaEventRecord(ev_join, s_aux);
    cudaStreamWaitEvent(0, ev_join, 0);

    attn_kernel<<<NPTS / 8, 256, attn_smem>>>(feature, b1, out);
}

// round 8
// speedup vs baseline: 3.3836x; 1.1109x over previous
#include <cuda_runtime.h>
#include <math.h>

#define BB   4
#define NN   4096
#define CC   128
#define KK1  16
#define KK2  8
#define TDD  64
#define KDIM 131
#define KPAD 144
#define RWS  512
#define NPTS (BB*NN)

typedef unsigned long long u64;

__device__ __forceinline__ u64 ffma2(u64 a, u64 b, u64 c) {
    u64 d;
    asm("fma.rn.f32x2 %0, %1, %2, %3;" : "=l"(d) : "l"(a), "l"(b), "l"(c));
    return d;
}
__device__ __forceinline__ u64 dup2(float x) {
    u64 d;
    asm("mov.b64 %0, {%1, %1};" : "=l"(d) : "r"(__float_as_int(x)));
    return d;
}
__device__ __forceinline__ void unpack2(u64 v, float& lo, float& hi) {
    int a, b;
    asm("mov.b64 {%0, %1}, %2;" : "=r"(a), "=r"(b) : "l"(v));
    lo = __int_as_float(a); hi = __int_as_float(b);
}

// ---------------- scratch ----------------
__device__ int   g_idx[NPTS*KK1];
// per point rows: [0:64)Pq [64:128)Pk [128:256)PvProj [256:320)Sq [320:384)Sk [384:512)SvProj
__device__ float g_P[(size_t)NPTS*RWS];
__device__ float g_WcT[KPAD*RWS];
__device__ float g_bias[RWS];

// ---------------- prep ----------------
__global__ void prep_kernel(const float* __restrict__ wq, const float* __restrict__ wk,
                            const float* __restrict__ wv, const float* __restrict__ bq,
                            const float* __restrict__ bk, const float* __restrict__ bv,
                            const float* __restrict__ w1) {
    int i = blockIdx.x * blockDim.x + threadIdx.x;
    const int total1 = KPAD * RWS;
    if (i < total1) {
        int k = i >> 9;
        int r = i & 511;
        float val = 0.f;
        if (k < KDIM) {
            if (r < 128) {                       // Pq | Pk
                const float* w = (r < 64) ? wq : wk;
                const float* row = w + (r & 63) * 262;
                val = (k < 3) ? row[k] : row[6 + (k - 3)];
            } else if (r < 256) {                // PvProj = w1 @ Pv
                int o = r - 128;
                float s = 0.f;
                for (int m = 0; m < TDD; ++m) {
                    const float* row = wv + m * 262;
                    float wvk = (k < 3) ? row[k] : row[6 + (k - 3)];
                    s = fmaf(w1[o * TDD + m], wvk, s);
                }
                val = s;
            } else if (r < 384) {                // Sq | Sk
                const float* w = (r < 320) ? wq : wk;
                const float* row = w + (r & 63) * 262;
                val = (k < 3) ? (row[3 + k] - row[k])
                              : (row[134 + (k - 3)] - row[6 + (k - 3)]);
            } else {                             // SvProj = w1 @ Sv
                int o = r - 384;
                float s = 0.f;
                for (int m = 0; m < TDD; ++m) {
                    const float* row = wv + m * 262;
                    float d = (k < 3) ? (row[3 + k] - row[k])
                                      : (row[134 + (k - 3)] - row[6 + (k - 3)]);
                    s = fmaf(w1[o * TDD + m], d, s);
                }
                val = s;
            }
        }
        g_WcT[(k << 9) + r] = val;
        return;
    }
    i -= total1;
    if (i < RWS) {
        float bval = 0.f;
        if (i >= 256 && i < 320) bval = bq[i - 256];
        else if (i >= 320 && i < 384) bval = bk[i - 320];
        else if (i >= 384) {
            int o = i - 384;
            float s = 0.f;
            for (int m = 0; m < TDD; ++m) s = fmaf(w1[o * TDD + m], bv[m], s);
            bval = s;
        }
        g_bias[i] = bval;
    }
}

// ---------------- kNN: warp per 2 queries, distributed sorted top-17 lists --------------
// Self is NOT excluded: d(self) = -|q|^2 is the strict minimum -> rank 0 always.
// Emit ranks 1..16 (== reference dropping idx[...,0]). Candidate LDS shared by 2 queries.
__global__ __launch_bounds__(512) void knn_kernel(const float* __restrict__ xyz) {
    extern __shared__ float4 sh[];                 // 4096 * 16B = 64KB
    const unsigned FULL = 0xffffffffu;
    const int b = blockIdx.x >> 7;                 // 128 blocks per batch
    const int qbase = (blockIdx.x & 127) * 32;     // 32 queries per block
    const int tid = threadIdx.x;
    const int w = tid >> 5, lane = tid & 31;
    const float* xb = xyz + (size_t)b * 3 * NN;

    for (int i = tid; i < NN; i += 512) {
        float x = xb[i], y = xb[NN + i], z = xb[2 * NN + i];
        float sq = fmaf(z, z, fmaf(y, y, x * x));
        sh[i] = make_float4(x, y, z, sq);
    }
    __syncthreads();

    const int qAi = qbase + 2 * w;
    const int qBi = qAi + 1;
    const float4 qA = sh[qAi];
    const float4 qB = sh[qBi];

    // ---- t = 0: evaluate first 32 candidates for both queries ----
    float dlA, dlB;
    int   ilA = lane, ilB = lane;
    {
        float4 c = sh[lane];
        dlA = fmaf(-2.0f, fmaf(qA.z, c.z, fmaf(qA.y, c.y, qA.x * c.x)), c.w);
        dlB = fmaf(-2.0f, fmaf(qB.z, c.z, fmaf(qB.y, c.y, qB.x * c.x)), c.w);
    }
    // fused bitonic sort across lanes for both lists (asc by dist, idx tie-break)
#pragma unroll
    for (int k = 2; k <= 32; k <<= 1) {
#pragma unroll
        for (int j = k >> 1; j > 0; j >>= 1) {
            float odA = __shfl_xor_sync(FULL, dlA, j);
            int   oiA = __shfl_xor_sync(FULL, ilA, j);
            float odB = __shfl_xor_sync(FULL, dlB, j);
            int   oiB = __shfl_xor_sync(FULL, ilB, j);
            bool lower = (lane & j) == 0;
            bool asc   = (lane & k) == 0;
            bool keepLt = (asc == lower);     // keep the smaller element
            bool ltA = (odA < dlA) || (odA == dlA && oiA < ilA);
            bool ltB = (odB < dlB) || (odB == dlB && oiB < ilB);
            bool swA = keepLt ? ltA : !ltA;
            bool swB = keepLt ? ltB : !ltB;
            if (swA) { dlA = odA; ilA = oiA; }
            if (swB) { dlB = odB; ilB = oiB; }
        }
    }
    float kthA = __shfl_sync(FULL, dlA, 16);   // 17th smallest
    float kthB = __shfl_sync(FULL, dlB, 16);

    // ---- main scan: one LDS per candidate serves both queries ----
#pragma unroll 2
    for (int t = 1; t < NN / 32; ++t) {
        const float4 c = sh[t * 32 + lane];
        float dA = fmaf(-2.0f, fmaf(qA.z, c.z, fmaf(qA.y, c.y, qA.x * c.x)), c.w);
        float dB = fmaf(-2.0f, fmaf(qB.z, c.z, fmaf(qB.y, c.y, qB.x * c.x)), c.w);

        unsigned mA = __ballot_sync(FULL, dA < kthA);
        unsigned mB = __ballot_sync(FULL, dB < kthB);
        if (mA) {
            do {
                const int src = __ffs(mA) - 1;
                mA &= mA - 1;
                const float dc = __shfl_sync(FULL, dA, src);
                const int   mc = t * 32 + src;
                const float up_d = __shfl_up_sync(FULL, dlA, 1);
                const int   up_i = __shfl_up_sync(FULL, ilA, 1);
                const bool here = dc < dlA;                 // strict: stable tie-break
                const bool prev = (lane > 0) && (dc < up_d);
                dlA = here ? (prev ? up_d : dc) : dlA;
                ilA = here ? (prev ? up_i : mc) : ilA;
            } while (mA);
            kthA = __shfl_sync(FULL, dlA, 16);
        }
        if (mB) {
            do {
                const int src = __ffs(mB) - 1;
                mB &= mB - 1;
                const float dc = __shfl_sync(FULL, dB, src);
                const int   mc = t * 32 + src;
                const float up_d = __shfl_up_sync(FULL, dlB, 1);
                const int   up_i = __shfl_up_sync(FULL, ilB, 1);
                const bool here = dc < dlB;
                const bool prev = (lane > 0) && (dc < up_d);
                dlB = here ? (prev ? up_d : dc) : dlB;
                ilB = here ? (prev ? up_i : mc) : ilB;
            } while (mB);
            kthB = __shfl_sync(FULL, dlB, 16);
        }
    }

    // ranks 1..16 (rank 0 == self)
    if (lane >= 1 && lane <= KK1) {
        g_idx[((size_t)b * NN + qAi) * KK1 + (lane - 1)] = ilA;
        g_idx[((size_t)b * NN + qBi) * KK1 + (lane - 1)] = ilB;
    }
}

// ---------------- SGEMM with packed f32x2 FMA ----------------
__global__ __launch_bounds__(256, 2) void gemm_kernel(const float* __restrict__ xyz,
                                                      const float* __restrict__ feature) {
    __shared__ __align__(16) float As[16][128];
    __shared__ __align__(16) float Bs[16][128];

    const int tid = threadIdx.x;
    const int tr = tid >> 4;
    const int tc = tid & 15;
    const int p0 = blockIdx.x * 128;
    const int b  = p0 >> 12;
    const int nl = p0 & (NN - 1);
    const int rowbase = blockIdx.y * 128;

    const int la_k = tid >> 4;
    const int la_r = (tid & 15) * 8;
    const int lb_k = tid >> 4;
    const int lb_j = (tid & 15) * 8;

    u64 acc[8][4];
#pragma unroll
    for (int i = 0; i < 8; ++i)
#pragma unroll
        for (int j = 0; j < 4; ++j) acc[i][j] = 0ull;

    float4 pa0, pa1, pb0, pb1;
    {
        const float* srcA = g_WcT + la_k * RWS + rowbase + la_r;
        pa0 = *(const float4*)srcA; pa1 = *(const float4*)(srcA + 4);
        int kg = lb_k;
        const float* row = (kg < 3) ? (xyz + ((size_t)b * 3 + kg) * NN)
                                    : (feature + ((size_t)b * CC + (kg - 3)) * NN);
        pb0 = *(const float4*)(row + nl + lb_j);
        pb1 = *(const float4*)(row + nl + lb_j + 4);
    }

    for (int kt = 0; kt < KPAD / 16; ++kt) {
        *(float4*)&As[la_k][la_r]     = pa0;
        *(float4*)&As[la_k][la_r + 4] = pa1;
        *(float4*)&Bs[lb_k][lb_j]     = pb0;
        *(float4*)&Bs[lb_k][lb_j + 4] = pb1;
        __syncthreads();
        if (kt + 1 < KPAD / 16) {
            const float* srcA = g_WcT + ((kt + 1) * 16 + la_k) * RWS + rowbase + la_r;
            pa0 = *(const float4*)srcA; pa1 = *(const float4*)(srcA + 4);
            int kg = (kt + 1) * 16 + lb_k;
            if (kg < KDIM) {
                const float* row = (kg < 3) ? (xyz + ((size_t)b * 3 + kg) * NN)
                                            : (feature + ((size_t)b * CC + (kg - 3)) * NN);
                pb0 = *(const float4*)(row + nl + lb_j);
                pb1 = *(const float4*)(row + nl + lb_j + 4);
            } else {
                pb0 = make_float4(0.f, 0.f, 0.f, 0.f);
                pb1 = pb0;
            }
        }
#pragma unroll
        for (int k = 0; k < 16; ++k) {
            float4 a0 = *(const float4*)&As[k][tr * 8];
            float4 a1 = *(const float4*)&As[k][tr * 8 + 4];
            ulonglong2 b0 = *(const ulonglong2*)&Bs[k][tc * 8];
            ulonglong2 b1 = *(const ulonglong2*)&Bs[k][tc * 8 + 4];
            u64 bp[4] = {b0.x, b0.y, b1.x, b1.y};
            float ar[8] = {a0.x, a0.y, a0.z, a0.w, a1.x, a1.y, a1.z, a1.w};
#pragma unroll
            for (int i = 0; i < 8; ++i) {
                u64 a2 = dup2(ar[i]);
#pragma unroll
                for (int j = 0; j < 4; ++j)
                    acc[i][j] = ffma2(a2, bp[j], acc[i][j]);
            }
        }
        __syncthreads();
    }

    const int gr = rowbase + tr * 8;
    float bias[8];
#pragma unroll
    for (int i = 0; i < 8; ++i) bias[i] = g_bias[gr + i];
    float r_[8][8];
#pragma unroll
    for (int i = 0; i < 8; ++i)
#pragma unroll
        for (int j = 0; j < 4; ++j)
            unpack2(acc[i][j], r_[i][2 * j], r_[i][2 * j + 1]);
#pragma unroll
    for (int j = 0; j < 8; ++j) {
        int p = p0 + tc * 8 + j;
        float* dst = g_P + (size_t)p * RWS + gr;
        float4 v0 = make_float4(r_[0][j] + bias[0], r_[1][j] + bias[1],
                                r_[2][j] + bias[2], r_[3][j] + bias[3]);
        float4 v1 = make_float4(r_[4][j] + bias[4], r_[5][j] + bias[5],
                                r_[6][j] + bias[6], r_[7][j] + bias[7]);
        *(float4*)dst       = v0;
        *(float4*)(dst + 4) = v1;
    }
}

// ---------------- attention ----------------
#define WARP_FLOATS 1632
#define SM_RES      (8*WARP_FLOATS)
#define SM_ATTN_TOT (SM_RES + 8*132)

__global__ __launch_bounds__(256, 3) void attn_kernel(const float* __restrict__ feature,
                                                      const float* __restrict__ b1,
                                                      float* __restrict__ out) {
    extern __shared__ __align__(16) float sm[];
    const int tid = threadIdx.x;
    const int w = tid >> 5, l = tid & 31;
    float* qw   = sm + w * WARP_FLOATS;
    float* kw   = qw + 8 * 68;
    float* resT = sm + SM_RES;

    const int gp = blockIdx.x * 8 + w;
    const int b  = gp >> 12;
    const int* ip = g_idx + (size_t)gp * KK1;
    const float* Pbase = g_P + ((size_t)(b << 12)) * RWS;
    const float* Sp    = g_P + (size_t)gp * RWS + 256;

    int c[16];
    {
        int4 t0 = ((const int4*)ip)[0]; int4 t1 = ((const int4*)ip)[1];
        int4 t2 = ((const int4*)ip)[2]; int4 t3 = ((const int4*)ip)[3];
        c[0]=t0.x; c[1]=t0.y; c[2]=t0.z; c[3]=t0.w;
        c[4]=t1.x; c[5]=t1.y; c[6]=t1.z; c[7]=t1.w;
        c[8]=t2.x; c[9]=t2.y; c[10]=t2.z; c[11]=t2.w;
        c[12]=t3.x; c[13]=t3.y; c[14]=t3.z; c[15]=t3.w;
    }

    // ---- gather q = Pq[c] + Sq ----
    {
        int a = l >> 2, qt = l & 3;
        const float4* src = (const float4*)(Pbase + (size_t)c[a] * RWS) + qt * 4;
        const float4* s4  = (const float4*)Sp + qt * 4;
        float4* dst = (float4*)(qw + a * 68 + qt * 16);
#pragma unroll
        for (int f = 0; f < 4; ++f) {
            float4 p = src[f], s = s4[f];
            dst[f] = make_float4(p.x + s.x, p.y + s.y, p.z + s.z, p.w + s.w);
        }
    }
    // ---- gather k = Pk[c] + Sk ----
    {
        int j = l >> 1, h = l & 1;
        const float4* src = (const float4*)(Pbase + (size_t)c[j] * RWS + 64 + h * 32);
        const float4* s4  = (const float4*)(Sp + 64 + h * 32);
        float4* dst = (float4*)(kw + j * 68 + h * 32);
#pragma unroll
        for (int f = 0; f < 8; ++f) {
            float4 p = src[f], s = s4[f];
            dst[f] = make_float4(p.x + s.x, p.y + s.y, p.z + s.z, p.w + s.w);
        }
    }
    __syncwarp();

    // ---- logits with packed f32x2 ----
    const int nq = l & 7, jg = l >> 3;
    u64 acc2[4] = {0ull, 0ull, 0ull, 0ull};
    const ulonglong2* qrow = (const ulonglong2*)(qw + nq * 68);
#pragma unroll
    for (int dc = 0; dc < 4; ++dc) {
        ulonglong2 qa = qrow[dc * 4 + 0], qb = qrow[dc * 4 + 1];
        ulonglong2 qc = qrow[dc * 4 + 2], qd = qrow[dc * 4 + 3];
#pragma unroll
        for (int j4 = 0; j4 < 4; ++j4) {
            const ulonglong2* kr = (const ulonglong2*)(kw + (j4 * 4 + jg) * 68);
            ulonglong2 ka = kr[dc * 4 + 0], kb = kr[dc * 4 + 1];
            ulonglong2 kc = kr[dc * 4 + 2], kd = kr[dc * 4 + 3];
            u64 s = acc2[j4];
            s = ffma2(qa.x, ka.x, s); s = ffma2(qa.y, ka.y, s);
            s = ffma2(qb.x, kb.x, s); s = ffma2(qb.y, kb.y, s);
            s = ffma2(qc.x, kc.x, s); s = ffma2(qc.y, kc.y, s);
            s = ffma2(qd.x, kd.x, s); s = ffma2(qd.y, kd.y, s);
            acc2[j4] = s;
        }
    }
    float acc[4];
#pragma unroll
    for (int j4 = 0; j4 < 4; ++j4) {
        float lo, hi; unpack2(acc2[j4], lo, hi);
        acc[j4] = lo + hi;
    }

    // ---- softmax over j per query row nq ----
    float mx = fmaxf(fmaxf(acc[0], acc[1]), fmaxf(acc[2], acc[3]));
    mx = fmaxf(mx, __shfl_xor_sync(0xffffffffu, mx, 8));
    mx = fmaxf(mx, __shfl_xor_sync(0xffffffffu, mx, 16));
    float e[4], ssum = 0.f;
#pragma unroll
    for (int j4 = 0; j4 < 4; ++j4) { e[j4] = __expf(acc[j4] - mx); ssum += e[j4]; }
    ssum += __shfl_xor_sync(0xffffffffu, ssum, 8);
    ssum += __shfl_xor_sync(0xffffffffu, ssum, 16);
    float inv = 1.0f / ssum;
    float wj[4];
#pragma unroll
    for (int j4 = 0; j4 < 4; ++j4) wj[j4] = e[j4] * inv;

    // ---- colsum over the 8 queries ----
#pragma unroll
    for (int off = 1; off < 8; off <<= 1)
#pragma unroll
        for (int j4 = 0; j4 < 4; ++j4)
            wj[j4] += __shfl_xor_sync(0xffffffffu, wj[j4], off);

    // ---- res128 = sum_j w[j]*PvProj[c_j] + wsum*SvProj (packed) ----
    u64 av0 = 0ull, av1 = 0ull;
#pragma unroll
    for (int j = 0; j < 16; ++j) {
        float wjv = __shfl_sync(0xffffffffu, wj[j >> 2], (j & 3) * 8);
        u64 w2 = dup2(wjv);
        ulonglong2 vv = *(const ulonglong2*)(Pbase + (size_t)c[j] * RWS + 128 + 4 * l);
        av0 = ffma2(w2, vv.x, av0);
        av1 = ffma2(w2, vv.y, av1);
    }
    float wsum = wj[0] + wj[1] + wj[2] + wj[3];
    wsum += __shfl_xor_sync(0xffffffffu, wsum, 8);
    wsum += __shfl_xor_sync(0xffffffffu, wsum, 16);
    {
        u64 w2 = dup2(wsum);
        ulonglong2 sv = *(const ulonglong2*)(Sp + 128 + 4 * l);
        av0 = ffma2(w2, sv.x, av0);
        av1 = ffma2(w2, sv.y, av1);
    }
    {
        float4 r;
        unpack2(av0, r.x, r.y);
        unpack2(av1, r.z, r.w);
        *(float4*)(resT + w * 132 + 4 * l) = r;
    }
    __syncthreads();

    // ---- out = res + b1 + feature ----
    const int o  = tid >> 1;
    const int pg = (tid & 1) * 4;
    const int gp0 = blockIdx.x * 8;
    const int bb = gp0 >> 12, nl = gp0 & (NN - 1);
    size_t base = ((size_t)bb * CC + o) * NN + nl + pg;
    float bo = b1[o];
    float4 fv = *(const float4*)(feature + base);
    float4 ov;
    ov.x = resT[(pg + 0) * 132 + o] + bo + fv.x;
    ov.y = resT[(pg + 1) * 132 + o] + bo + fv.y;
    ov.z = resT[(pg + 2) * 132 + o] + bo + fv.z;
    ov.w = resT[(pg + 3) * 132 + o] + bo + fv.w;
    *(float4*)(out + base) = ov;
}

// ---------------- launch: fork(knn || prep->gemm) -> join -> attn ----------------
extern "C" void kernel_launch(void* const* d_in, const int* in_sizes, int n_in,
                              void* d_out, int out_size) {
    const float* feature = (const float*)d_in[0];
    const float* xyz     = (const float*)d_in[1];
    const float* wq      = (const float*)d_in[2];
    const float* bq      = (const float*)d_in[3];
    const float* wk      = (const float*)d_in[4];
    const float* bk      = (const float*)d_in[5];
    const float* wv      = (const float*)d_in[6];
    const float* bv      = (const float*)d_in[7];
    const float* w1      = (const float*)d_in[8];
    const float* b1      = (const float*)d_in[9];
    float* out = (float*)d_out;

    static cudaStream_t s_aux = []{
        cudaStream_t s; cudaStreamCreateWithFlags(&s, cudaStreamNonBlocking); return s; }();
    static cudaEvent_t ev_fork = []{
        cudaEvent_t e; cudaEventCreateWithFlags(&e, cudaEventDisableTiming); return e; }();
    static cudaEvent_t ev_join = []{
        cudaEvent_t e; cudaEventCreateWithFlags(&e, cudaEventDisableTiming); return e; }();
    static bool attr_done = []{
        cudaFuncSetAttribute(knn_kernel,  cudaFuncAttributeMaxDynamicSharedMemorySize, NN * 16);
        cudaFuncSetAttribute(attn_kernel, cudaFuncAttributeMaxDynamicSharedMemorySize, SM_ATTN_TOT * 4);
        return true; }();
    (void)attr_done;

    const int knn_smem  = NN * 16;
    const int attn_smem = SM_ATTN_TOT * 4;

    cudaEventRecord(ev_fork, 0);
    cudaStreamWaitEvent(s_aux, ev_fork, 0);

    {
        int total = KPAD * RWS + RWS;
        prep_kernel<<<(total + 255) / 256, 256, 0, s_aux>>>(wq, wk, wv, bq, bk, bv, w1);
    }
    gemm_kernel<<<dim3(NPTS / 128, RWS / 128), 256, 0, s_aux>>>(xyz, feature);

    knn_kernel<<<BB * 128, 512, knn_smem>>>(xyz);

    cudaEventRecord(ev_join, s_aux);
    cudaStreamWaitEvent(0, ev_join, 0);

    attn_kernel<<<NPTS / 8, 256, attn_smem>>>(feature, b1, out);
}